// round 1
// baseline (speedup 1.0000x reference)
#include <cuda_runtime.h>
#include <math.h>
#include <stdint.h>

#define DI   1536
#define DM   768
#define NST  16
#define DTR  48
#define BB   2
#define LL   1024
#define NSEG 8
#define SEGL (LL / NSEG)

// ---------------- scratch (device globals; no allocation allowed) ----------------
__device__ float g_xz[(size_t)BB * LL * 2 * DI];      // in_proj output (x | z)
__device__ float g_xc0[(size_t)BB * LL * DI];         // conv+silu fwd
__device__ float g_xc1[(size_t)BB * LL * DI];         // conv+silu rev (reversed coords)
__device__ float g_xdbl0[(size_t)BB * LL * 80];       // x_proj out fwd: [dt(48)|B(16)|C(16)]
__device__ float g_xdbl1[(size_t)BB * LL * 80];
__device__ float g_delta0[(size_t)BB * LL * DI];      // softplus(dt@W + b) fwd
__device__ float g_delta1[(size_t)BB * LL * DI];
__device__ float g_segP0[(size_t)BB * NSEG * DI * NST];
__device__ float g_segP1[(size_t)BB * NSEG * DI * NST];
__device__ float g_segH0[(size_t)BB * NSEG * DI * NST];
__device__ float g_segH1[(size_t)BB * NSEG * DI * NST];
__device__ float g_ys0[(size_t)BB * LL * DI];         // fwd branch gated output
__device__ float g_ys1[(size_t)BB * LL * DI];         // rev branch gated output (unflipped)

// ---------------- generic NT GEMM: C[M,N] = A[M,K] * B[N,K]^T ----------------
struct GArgs {
    const float* A[2];
    const float* A2[2];    // optional second A (summed into A) when ASUM
    const float* B[2];
    float*       C[2];
    const float* bias[2];
    int M, N, K, lda, ldb, ldc;
};

// EPI: 0 = plain store, 1 = softplus(acc + bias[n])
template <int BM, int BN, int BK, int TM, int TN, int EPI, bool ASUM>
__global__ void __launch_bounds__((BM / TM) * (BN / TN))
gemm_nt(GArgs g) {
    constexpr int TX = BN / TN;
    constexpr int TY = BM / TM;
    constexpr int THREADS = TX * TY;

    const int br = blockIdx.z;
    const float* __restrict__ A  = g.A[br];
    const float* __restrict__ A2 = g.A2[br];
    const float* __restrict__ B  = g.B[br];
    float* __restrict__ C        = g.C[br];
    const float* __restrict__ bias = g.bias[br];

    __shared__ __align__(16) float As[BK][BM + 4];
    __shared__ __align__(16) float Bs[BK][BN + 4];

    const int tid = threadIdx.x;
    const int tx = tid % TX;
    const int ty = tid / TX;
    const int bm = blockIdx.y * BM;
    const int bn = blockIdx.x * BN;

    float acc[TM][TN];
#pragma unroll
    for (int i = 0; i < TM; i++)
#pragma unroll
        for (int j = 0; j < TN; j++) acc[i][j] = 0.f;

    for (int kt = 0; kt < g.K; kt += BK) {
        // load A tile (transposed into smem)
#pragma unroll 4
        for (int i = tid; i < BM * BK; i += THREADS) {
            int m = i / BK, k = i % BK;
            float v = A[(size_t)(bm + m) * g.lda + kt + k];
            if (ASUM) v += A2[(size_t)(bm + m) * g.lda + kt + k];
            As[k][m] = v;
        }
#pragma unroll 4
        for (int i = tid; i < BN * BK; i += THREADS) {
            int n = i / BK, k = i % BK;
            Bs[k][n] = B[(size_t)(bn + n) * g.ldb + kt + k];
        }
        __syncthreads();

#pragma unroll
        for (int k = 0; k < BK; k++) {
            float a_frag[TM], b_frag[TN];
#pragma unroll
            for (int i = 0; i < TM; i++) a_frag[i] = As[k][ty * TM + i];
#pragma unroll
            for (int j = 0; j < TN; j++) b_frag[j] = Bs[k][tx * TN + j];
#pragma unroll
            for (int i = 0; i < TM; i++)
#pragma unroll
                for (int j = 0; j < TN; j++)
                    acc[i][j] = fmaf(a_frag[i], b_frag[j], acc[i][j]);
        }
        __syncthreads();
    }

#pragma unroll
    for (int i = 0; i < TM; i++) {
        const int m = bm + ty * TM + i;
#pragma unroll
        for (int j = 0; j < TN; j++) {
            const int n = bn + tx * TN + j;
            float v = acc[i][j];
            if (EPI == 1) {
                v += bias[n];
                v = (v > 20.f) ? v : log1pf(__expf(v));
            }
            C[(size_t)m * g.ldc + n] = v;
        }
    }
}

// ---------------- depthwise causal conv (K=4) + SiLU, both branches ----------------
__device__ __forceinline__ float silu_f(float v) {
    return v / (1.f + __expf(-v));
}

__global__ void __launch_bounds__(256)
conv_silu_k(const float* __restrict__ cw0, const float* __restrict__ cb0,
            const float* __restrict__ cw1, const float* __restrict__ cb1) {
    size_t idx = (size_t)blockIdx.x * 256 + threadIdx.x;
    if (idx >= (size_t)BB * LL * DI) return;
    const int d = (int)(idx % DI);
    const int l = (int)((idx / DI) % LL);
    const int b = (int)(idx / ((size_t)DI * LL));

    const float* xzb = g_xz + (size_t)b * LL * 2 * DI + d;  // x column d, stride 2*DI

    float w0[4], w1[4];
#pragma unroll
    for (int k = 0; k < 4; k++) { w0[k] = cw0[d * 4 + k]; w1[k] = cw1[d * 4 + k]; }

    // forward branch: out[l] = b + sum_k x[l-3+k] * w[k]
    float s0 = cb0[d];
#pragma unroll
    for (int k = 0; k < 4; k++) {
        int ls = l - 3 + k;
        if (ls >= 0) s0 += xzb[(size_t)ls * 2 * DI] * w0[k];
    }
    g_xc0[idx] = silu_f(s0);

    // reverse branch (reversed coords): tap = x[L-1-l+3-k], valid when l-3+k >= 0
    float s1 = cb1[d];
#pragma unroll
    for (int k = 0; k < 4; k++) {
        if (l - 3 + k >= 0) {
            int src = LL - 1 - l + 3 - k;
            s1 += xzb[(size_t)src * 2 * DI] * w1[k];
        }
    }
    g_xc1[idx] = silu_f(s1);
}

// ---------------- selective scan, chunked (pass A: segment propagators) ----------------
__global__ void __launch_bounds__(128)
scan_passA(const float* __restrict__ AlogF, const float* __restrict__ AlogR) {
    const int tid = threadIdx.x;
    const int d = blockIdx.x * 128 + tid;
    const int seg = blockIdx.y;
    const int b = blockIdx.z & 1;
    const int br = blockIdx.z >> 1;

    const float* Alog   = br ? AlogR   : AlogF;
    const float* gdelta = br ? g_delta1 : g_delta0;
    const float* gxc    = br ? g_xc1    : g_xc0;
    const float* gxdbl  = br ? g_xdbl1  : g_xdbl0;
    float* gP = br ? g_segP1 : g_segP0;
    float* gH = br ? g_segH1 : g_segH0;

    float An[NST];
    bool fast = true;
#pragma unroll
    for (int n = 0; n < NST; n++) {
        An[n] = -__expf(Alog[d * NST + n]);
        if (fabsf(An[n] + (float)(n + 1)) > 1e-3f) fast = false;
    }

    float H[NST], P[NST];
#pragma unroll
    for (int n = 0; n < NST; n++) { H[n] = 0.f; P[n] = 1.f; }

    const size_t rowbase = (size_t)b * LL + (size_t)seg * SEGL;
    const float* dp = gdelta + rowbase * DI + d;
    const float* xp = gxc + rowbase * DI + d;
    const float* bc = gxdbl + rowbase * 80 + 48;

    __shared__ __align__(16) float sBC[32 * 32];

    for (int lc = 0; lc < SEGL; lc += 32) {
        __syncthreads();
        for (int i = tid; i < 32 * 32; i += 128) {
            int li = i >> 5, c = i & 31;
            sBC[i] = bc[(size_t)(lc + li) * 80 + c];
        }
        __syncthreads();
        for (int li = 0; li < 32; li++) {
            const int l = lc + li;
            const float delta = dp[(size_t)l * DI];
            const float x = xp[(size_t)l * DI];
            const float dx = delta * x;
            float bv[NST];
            const float4* q = (const float4*)&sBC[li * 32];
            ((float4*)bv)[0] = q[0]; ((float4*)bv)[1] = q[1];
            ((float4*)bv)[2] = q[2]; ((float4*)bv)[3] = q[3];
            if (fast) {
                const float e = __expf(-delta);
                float p = 1.f;
#pragma unroll
                for (int n = 0; n < NST; n++) {
                    p *= e;
                    H[n] = fmaf(p, H[n], dx * bv[n]);
                    P[n] *= p;
                }
            } else {
#pragma unroll
                for (int n = 0; n < NST; n++) {
                    float da = __expf(delta * An[n]);
                    H[n] = fmaf(da, H[n], dx * bv[n]);
                    P[n] *= da;
                }
            }
        }
    }

    const size_t o = (((size_t)b * NSEG + seg) * DI + d) * NST;
#pragma unroll
    for (int i = 0; i < 4; i++) {
        ((float4*)&gP[o])[i] = ((float4*)P)[i];
        ((float4*)&gH[o])[i] = ((float4*)H)[i];
    }
}

// ---------------- pass C: combine segment states, re-scan, emit gated output ----------------
__global__ void __launch_bounds__(128)
scan_passC(const float* __restrict__ AlogF, const float* __restrict__ AlogR,
           const float* __restrict__ Df, const float* __restrict__ Dr) {
    const int tid = threadIdx.x;
    const int d = blockIdx.x * 128 + tid;
    const int seg = blockIdx.y;
    const int b = blockIdx.z & 1;
    const int br = blockIdx.z >> 1;

    const float* Alog   = br ? AlogR   : AlogF;
    const float* gdelta = br ? g_delta1 : g_delta0;
    const float* gxc    = br ? g_xc1    : g_xc0;
    const float* gxdbl  = br ? g_xdbl1  : g_xdbl0;
    const float* gP = br ? g_segP1 : g_segP0;
    const float* gH = br ? g_segH1 : g_segH0;
    float* ys = br ? g_ys1 : g_ys0;

    float An[NST];
    bool fast = true;
#pragma unroll
    for (int n = 0; n < NST; n++) {
        An[n] = -__expf(Alog[d * NST + n]);
        if (fabsf(An[n] + (float)(n + 1)) > 1e-3f) fast = false;
    }

    // combine previous segments: h = P_t * h + H_t, exact linear-recurrence algebra
    float h[NST];
#pragma unroll
    for (int n = 0; n < NST; n++) h[n] = 0.f;
    for (int t = 0; t < seg; t++) {
        const size_t o = (((size_t)b * NSEG + t) * DI + d) * NST;
        float Pt[NST], Ht[NST];
#pragma unroll
        for (int i = 0; i < 4; i++) {
            ((float4*)Pt)[i] = ((const float4*)&gP[o])[i];
            ((float4*)Ht)[i] = ((const float4*)&gH[o])[i];
        }
#pragma unroll
        for (int n = 0; n < NST; n++) h[n] = fmaf(Pt[n], h[n], Ht[n]);
    }

    const float Dd = (br ? Dr : Df)[d];
    const size_t rowbase = (size_t)b * LL + (size_t)seg * SEGL;
    const float* dp = gdelta + rowbase * DI + d;
    const float* xp = gxc + rowbase * DI + d;
    const float* bc = gxdbl + rowbase * 80 + 48;
    const float* gz = g_xz + (size_t)b * LL * 2 * DI + DI + d;  // z column

    __shared__ __align__(16) float sBC[32 * 32];

    for (int lc = 0; lc < SEGL; lc += 32) {
        __syncthreads();
        for (int i = tid; i < 32 * 32; i += 128) {
            int li = i >> 5, c = i & 31;
            sBC[i] = bc[(size_t)(lc + li) * 80 + c];
        }
        __syncthreads();
        for (int li = 0; li < 32; li++) {
            const int l = lc + li;
            const float delta = dp[(size_t)l * DI];
            const float x = xp[(size_t)l * DI];
            const float dx = delta * x;
            float bv[NST], cv[NST];
            const float4* q = (const float4*)&sBC[li * 32];
            ((float4*)bv)[0] = q[0]; ((float4*)bv)[1] = q[1];
            ((float4*)bv)[2] = q[2]; ((float4*)bv)[3] = q[3];
            ((float4*)cv)[0] = q[4]; ((float4*)cv)[1] = q[5];
            ((float4*)cv)[2] = q[6]; ((float4*)cv)[3] = q[7];
            float y = 0.f;
            if (fast) {
                const float e = __expf(-delta);
                float p = 1.f;
#pragma unroll
                for (int n = 0; n < NST; n++) {
                    p *= e;
                    h[n] = fmaf(p, h[n], dx * bv[n]);
                    y = fmaf(h[n], cv[n], y);
                }
            } else {
#pragma unroll
                for (int n = 0; n < NST; n++) {
                    float da = __expf(delta * An[n]);
                    h[n] = fmaf(da, h[n], dx * bv[n]);
                    y = fmaf(h[n], cv[n], y);
                }
            }
            const int gl = seg * SEGL + l;
            const int lo = br ? (LL - 1 - gl) : gl;  // un-flip reverse branch here
            const float zv = gz[(size_t)lo * 2 * DI];
            const float out = (y + x * Dd) * silu_f(zv);
            ys[((size_t)b * LL + lo) * DI + d] = out;
        }
    }
}

// ---------------- launch ----------------
extern "C" void kernel_launch(void* const* d_in, const int* in_sizes, int n_in,
                              void* d_out, int out_size) {
    const float* hidden     = (const float*)d_in[0];
    const float* in_proj_w  = (const float*)d_in[1];
    const float* conv_w     = (const float*)d_in[2];
    const float* conv_b     = (const float*)d_in[3];
    const float* x_proj_w   = (const float*)d_in[4];
    const float* dt_proj_w  = (const float*)d_in[5];
    const float* dt_proj_b  = (const float*)d_in[6];
    const float* A_log      = (const float*)d_in[7];
    const float* Dv         = (const float*)d_in[8];
    const float* conv_w_b   = (const float*)d_in[9];
    const float* conv_b_b   = (const float*)d_in[10];
    const float* x_proj_w_b = (const float*)d_in[11];
    const float* dt_proj_w_b= (const float*)d_in[12];
    const float* dt_proj_b_b= (const float*)d_in[13];
    const float* A_b_log    = (const float*)d_in[14];
    const float* D_b        = (const float*)d_in[15];
    const float* out_proj_w = (const float*)d_in[16];
    float* out = (float*)d_out;

    float *p_xz, *p_xc0, *p_xc1, *p_xdbl0, *p_xdbl1, *p_delta0, *p_delta1, *p_ys0, *p_ys1;
    cudaGetSymbolAddress((void**)&p_xz, g_xz);
    cudaGetSymbolAddress((void**)&p_xc0, g_xc0);
    cudaGetSymbolAddress((void**)&p_xc1, g_xc1);
    cudaGetSymbolAddress((void**)&p_xdbl0, g_xdbl0);
    cudaGetSymbolAddress((void**)&p_xdbl1, g_xdbl1);
    cudaGetSymbolAddress((void**)&p_delta0, g_delta0);
    cudaGetSymbolAddress((void**)&p_delta1, g_delta1);
    cudaGetSymbolAddress((void**)&p_ys0, g_ys0);
    cudaGetSymbolAddress((void**)&p_ys1, g_ys1);

    const int M = BB * LL;  // 2048

    // 1) xz = hidden @ in_proj_w^T   (2048 x 3072, K=768)
    {
        GArgs a{};
        a.A[0] = a.A[1] = hidden;
        a.B[0] = a.B[1] = in_proj_w;
        a.C[0] = a.C[1] = p_xz;
        a.bias[0] = a.bias[1] = nullptr;
        a.A2[0] = a.A2[1] = nullptr;
        a.M = M; a.N = 2 * DI; a.K = DM; a.lda = DM; a.ldb = DM; a.ldc = 2 * DI;
        gemm_nt<128, 128, 16, 8, 8, 0, false><<<dim3(24, 16, 1), 256>>>(a);
    }

    // 2) depthwise causal conv + silu (both branches)
    conv_silu_k<<<(unsigned)(((size_t)BB * LL * DI + 255) / 256), 256>>>(
        conv_w, conv_b, conv_w_b, conv_b_b);

    // 3) x_dbl = xc @ x_proj_w^T   (2048 x 80, K=1536), both branches
    {
        GArgs a{};
        a.A[0] = p_xc0; a.A[1] = p_xc1;
        a.B[0] = x_proj_w; a.B[1] = x_proj_w_b;
        a.C[0] = p_xdbl0; a.C[1] = p_xdbl1;
        a.bias[0] = a.bias[1] = nullptr;
        a.A2[0] = a.A2[1] = nullptr;
        a.M = M; a.N = 80; a.K = DI; a.lda = DI; a.ldb = DI; a.ldc = 80;
        gemm_nt<64, 80, 32, 4, 5, 0, false><<<dim3(1, 32, 2), 256>>>(a);
    }

    // 4) delta = softplus(dt @ dt_proj_w^T + bias)  (2048 x 1536, K=48), both branches
    {
        GArgs a{};
        a.A[0] = p_xdbl0; a.A[1] = p_xdbl1;
        a.B[0] = dt_proj_w; a.B[1] = dt_proj_w_b;
        a.C[0] = p_delta0; a.C[1] = p_delta1;
        a.bias[0] = dt_proj_b; a.bias[1] = dt_proj_b_b;
        a.A2[0] = a.A2[1] = nullptr;
        a.M = M; a.N = DI; a.K = DTR; a.lda = 80; a.ldb = DTR; a.ldc = DI;
        gemm_nt<128, 128, 16, 8, 8, 1, false><<<dim3(12, 16, 2), 256>>>(a);
    }

    // 5) scan pass A (segment propagators; seg 7 not needed downstream)
    scan_passA<<<dim3(DI / 128, NSEG - 1, 4), 128>>>(A_log, A_b_log);

    // 6) scan pass C (combine + emit gated branch outputs)
    scan_passC<<<dim3(DI / 128, NSEG, 4), 128>>>(A_log, A_b_log, Dv, D_b);

    // 7) out = (ys0 + ys1) @ out_proj_w^T   (2048 x 768, K=1536); A-sum fused
    {
        GArgs a{};
        a.A[0] = a.A[1] = p_ys0;
        a.A2[0] = a.A2[1] = p_ys1;
        a.B[0] = a.B[1] = out_proj_w;
        a.C[0] = a.C[1] = out;
        a.bias[0] = a.bias[1] = nullptr;
        a.M = M; a.N = DM; a.K = DI; a.lda = DI; a.ldb = DI; a.ldc = DM;
        gemm_nt<128, 64, 16, 8, 4, 0, true><<<dim3(12, 16, 1), 256>>>(a);
    }
}

// round 2
// speedup vs baseline: 2.0332x; 2.0332x over previous
#include <cuda_runtime.h>
#include <math.h>
#include <stdint.h>

#define DI   1536
#define DM   768
#define NST  16
#define DTR  48
#define BB   2
#define LL   1024
#define NSEG 8
#define SEGL (LL / NSEG)

// ---------------- scratch (device globals; no allocation allowed) ----------------
__device__ float g_xz[(size_t)BB * LL * 2 * DI];      // in_proj output (x | z)
__device__ float g_xc0[(size_t)BB * LL * DI];         // conv+silu fwd
__device__ float g_xc1[(size_t)BB * LL * DI];         // conv+silu rev (reversed coords)
__device__ float g_xdbl0[(size_t)BB * LL * 80];       // x_proj out fwd: [dt(48)|B(16)|C(16)]
__device__ float g_xdbl1[(size_t)BB * LL * 80];
__device__ float g_delta0[(size_t)BB * LL * DI];      // softplus(dt@W + b) fwd
__device__ float g_delta1[(size_t)BB * LL * DI];
__device__ float g_segP0[(size_t)BB * NSEG * DI * NST];
__device__ float g_segP1[(size_t)BB * NSEG * DI * NST];
__device__ float g_segH0[(size_t)BB * NSEG * DI * NST];
__device__ float g_segH1[(size_t)BB * NSEG * DI * NST];
__device__ float g_ys0[(size_t)BB * LL * DI];         // fwd branch gated output
__device__ float g_ys1[(size_t)BB * LL * DI];         // rev branch gated output (unflipped)

// ---------------- pipelined NT GEMM: C[M,N] = A[M,K] * B[N,K]^T ----------------
struct GArgs {
    const float* A[2];
    const float* A2[2];    // optional second A (summed into A) when ASUM
    const float* B[2];
    float*       C[2];
    const float* bias[2];
    int M, N, K, lda, ldb, ldc;
};

// EPI: 0 = plain store, 1 = softplus(acc + bias[n])
// Requirements: M%BM==0, N%BN==0, K%BK==0, lda/ldb/ldc %4==0,
//               BM*BK/4 % THREADS == 0, BN*BK/4 % THREADS == 0.
template <int BM, int BN, int BK, int TM, int TN, int EPI, bool ASUM>
__global__ void __launch_bounds__((BM / TM) * (BN / TN))
gemm_pipe(GArgs g) {
    constexpr int TX = BN / TN;
    constexpr int TY = BM / TM;
    constexpr int THREADS = TX * TY;
    constexpr int PAD = 4;
    constexpr int KQ = BK / 4;                // float4 per row of a k-tile
    constexpr int AV = (BM * KQ) / THREADS;   // float4 per thread (A tile)
    constexpr int BV = (BN * KQ) / THREADS;

    const int br = blockIdx.z;
    const float* __restrict__ A  = g.A[br];
    const float* __restrict__ A2 = g.A2[br];
    const float* __restrict__ B  = g.B[br];
    float* __restrict__ C        = g.C[br];
    const float* __restrict__ bias = g.bias[br];

    __shared__ __align__(16) float As[2][BK][BM + PAD];
    __shared__ __align__(16) float Bs[2][BK][BN + PAD];

    const int tid = threadIdx.x;
    const int tx = tid % TX;
    const int ty = tid / TX;
    const int bm = blockIdx.y * BM;
    const int bn = blockIdx.x * BN;

    const int lda = g.lda, ldb = g.ldb;

    float4 ra[AV], rb[BV];

    // -------- tile load helpers (register staging) --------
    auto ldg_tile = [&](int kt) {
#pragma unroll
        for (int t = 0; t < AV; t++) {
            int i = tid + t * THREADS;
            int m = i / KQ, kq = i % KQ;
            size_t off = (size_t)(bm + m) * lda + kt + kq * 4;
            float4 v = *(const float4*)(A + off);
            if (ASUM) {
                float4 w = *(const float4*)(A2 + off);
                v.x += w.x; v.y += w.y; v.z += w.z; v.w += w.w;
            }
            ra[t] = v;
        }
#pragma unroll
        for (int t = 0; t < BV; t++) {
            int i = tid + t * THREADS;
            int n = i / KQ, kq = i % KQ;
            rb[t] = *(const float4*)(B + (size_t)(bn + n) * ldb + kt + kq * 4);
        }
    };
    auto sts_tile = [&](int buf) {
#pragma unroll
        for (int t = 0; t < AV; t++) {
            int i = tid + t * THREADS;
            int m = i / KQ, kq = i % KQ;
            As[buf][kq * 4 + 0][m] = ra[t].x;
            As[buf][kq * 4 + 1][m] = ra[t].y;
            As[buf][kq * 4 + 2][m] = ra[t].z;
            As[buf][kq * 4 + 3][m] = ra[t].w;
        }
#pragma unroll
        for (int t = 0; t < BV; t++) {
            int i = tid + t * THREADS;
            int n = i / KQ, kq = i % KQ;
            Bs[buf][kq * 4 + 0][n] = rb[t].x;
            Bs[buf][kq * 4 + 1][n] = rb[t].y;
            Bs[buf][kq * 4 + 2][n] = rb[t].z;
            Bs[buf][kq * 4 + 3][n] = rb[t].w;
        }
    };

    float acc[TM][TN];
#pragma unroll
    for (int i = 0; i < TM; i++)
#pragma unroll
        for (int j = 0; j < TN; j++) acc[i][j] = 0.f;

    auto compute = [&](int buf) {
#pragma unroll
        for (int k = 0; k < BK; k++) {
            float a_frag[TM], b_frag[TN];
            if constexpr (TM % 4 == 0) {
#pragma unroll
                for (int q = 0; q < TM / 4; q++)
                    *(float4*)&a_frag[q * 4] = *(const float4*)&As[buf][k][ty * TM + q * 4];
            } else {
#pragma unroll
                for (int i = 0; i < TM; i++) a_frag[i] = As[buf][k][ty * TM + i];
            }
            if constexpr (TN % 4 == 0) {
#pragma unroll
                for (int q = 0; q < TN / 4; q++)
                    *(float4*)&b_frag[q * 4] = *(const float4*)&Bs[buf][k][tx * TN + q * 4];
            } else {
#pragma unroll
                for (int j = 0; j < TN; j++) b_frag[j] = Bs[buf][k][tx * TN + j];
            }
#pragma unroll
            for (int i = 0; i < TM; i++)
#pragma unroll
                for (int j = 0; j < TN; j++)
                    acc[i][j] = fmaf(a_frag[i], b_frag[j], acc[i][j]);
        }
    };

    // -------- pipelined mainloop --------
    const int nk = g.K / BK;
    ldg_tile(0);
    sts_tile(0);
    __syncthreads();
    for (int kt = 1; kt < nk; kt++) {
        ldg_tile(kt * BK);                 // global latency hidden by compute below
        compute((kt - 1) & 1);
        sts_tile(kt & 1);
        __syncthreads();
    }
    compute((nk - 1) & 1);

    // -------- epilogue --------
#pragma unroll
    for (int i = 0; i < TM; i++) {
        const int m = bm + ty * TM + i;
#pragma unroll
        for (int j = 0; j < TN; j++) {
            const int n = bn + tx * TN + j;
            float v = acc[i][j];
            if (EPI == 1) {
                v += bias[n];
                v = (v > 20.f) ? v : log1pf(__expf(v));
            }
            C[(size_t)m * g.ldc + n] = v;
        }
    }
}

// ---------------- depthwise causal conv (K=4) + SiLU, both branches ----------------
__device__ __forceinline__ float silu_f(float v) {
    return v / (1.f + __expf(-v));
}

__global__ void __launch_bounds__(256)
conv_silu_k(const float* __restrict__ cw0, const float* __restrict__ cb0,
            const float* __restrict__ cw1, const float* __restrict__ cb1) {
    size_t idx = (size_t)blockIdx.x * 256 + threadIdx.x;
    if (idx >= (size_t)BB * LL * DI) return;
    const int d = (int)(idx % DI);
    const int l = (int)((idx / DI) % LL);
    const int b = (int)(idx / ((size_t)DI * LL));

    const float* xzb = g_xz + (size_t)b * LL * 2 * DI + d;  // x column d, stride 2*DI

    float w0[4], w1[4];
#pragma unroll
    for (int k = 0; k < 4; k++) { w0[k] = cw0[d * 4 + k]; w1[k] = cw1[d * 4 + k]; }

    float s0 = cb0[d];
#pragma unroll
    for (int k = 0; k < 4; k++) {
        int ls = l - 3 + k;
        if (ls >= 0) s0 += xzb[(size_t)ls * 2 * DI] * w0[k];
    }
    g_xc0[idx] = silu_f(s0);

    float s1 = cb1[d];
#pragma unroll
    for (int k = 0; k < 4; k++) {
        if (l - 3 + k >= 0) {
            int src = LL - 1 - l + 3 - k;
            s1 += xzb[(size_t)src * 2 * DI] * w1[k];
        }
    }
    g_xc1[idx] = silu_f(s1);
}

// ---------------- selective scan, chunked (pass A: segment propagators) ----------------
__global__ void __launch_bounds__(128)
scan_passA(const float* __restrict__ AlogF, const float* __restrict__ AlogR) {
    const int tid = threadIdx.x;
    const int d = blockIdx.x * 128 + tid;
    const int seg = blockIdx.y;
    const int b = blockIdx.z & 1;
    const int br = blockIdx.z >> 1;

    const float* Alog   = br ? AlogR   : AlogF;
    const float* gdelta = br ? g_delta1 : g_delta0;
    const float* gxc    = br ? g_xc1    : g_xc0;
    const float* gxdbl  = br ? g_xdbl1  : g_xdbl0;
    float* gP = br ? g_segP1 : g_segP0;
    float* gH = br ? g_segH1 : g_segH0;

    float An[NST];
    bool fast = true;
#pragma unroll
    for (int n = 0; n < NST; n++) {
        An[n] = -__expf(Alog[d * NST + n]);
        if (fabsf(An[n] + (float)(n + 1)) > 1e-3f) fast = false;
    }

    float H[NST], P[NST];
#pragma unroll
    for (int n = 0; n < NST; n++) { H[n] = 0.f; P[n] = 1.f; }

    const size_t rowbase = (size_t)b * LL + (size_t)seg * SEGL;
    const float* dp = gdelta + rowbase * DI + d;
    const float* xp = gxc + rowbase * DI + d;
    const float* bc = gxdbl + rowbase * 80 + 48;

    __shared__ __align__(16) float sBC[32 * 32];

    for (int lc = 0; lc < SEGL; lc += 32) {
        __syncthreads();
        for (int i = tid; i < 32 * 32; i += 128) {
            int li = i >> 5, c = i & 31;
            sBC[i] = bc[(size_t)(lc + li) * 80 + c];
        }
        __syncthreads();
        for (int li = 0; li < 32; li++) {
            const int l = lc + li;
            const float delta = dp[(size_t)l * DI];
            const float x = xp[(size_t)l * DI];
            const float dx = delta * x;
            float bv[NST];
            const float4* q = (const float4*)&sBC[li * 32];
            ((float4*)bv)[0] = q[0]; ((float4*)bv)[1] = q[1];
            ((float4*)bv)[2] = q[2]; ((float4*)bv)[3] = q[3];
            if (fast) {
                const float e = __expf(-delta);
                float p = 1.f;
#pragma unroll
                for (int n = 0; n < NST; n++) {
                    p *= e;
                    H[n] = fmaf(p, H[n], dx * bv[n]);
                    P[n] *= p;
                }
            } else {
#pragma unroll
                for (int n = 0; n < NST; n++) {
                    float da = __expf(delta * An[n]);
                    H[n] = fmaf(da, H[n], dx * bv[n]);
                    P[n] *= da;
                }
            }
        }
    }

    const size_t o = (((size_t)b * NSEG + seg) * DI + d) * NST;
#pragma unroll
    for (int i = 0; i < 4; i++) {
        ((float4*)&gP[o])[i] = ((float4*)P)[i];
        ((float4*)&gH[o])[i] = ((float4*)H)[i];
    }
}

// ---------------- pass C: combine segment states, re-scan, emit gated output ----------------
__global__ void __launch_bounds__(128)
scan_passC(const float* __restrict__ AlogF, const float* __restrict__ AlogR,
           const float* __restrict__ Df, const float* __restrict__ Dr) {
    const int tid = threadIdx.x;
    const int d = blockIdx.x * 128 + tid;
    const int seg = blockIdx.y;
    const int b = blockIdx.z & 1;
    const int br = blockIdx.z >> 1;

    const float* Alog   = br ? AlogR   : AlogF;
    const float* gdelta = br ? g_delta1 : g_delta0;
    const float* gxc    = br ? g_xc1    : g_xc0;
    const float* gxdbl  = br ? g_xdbl1  : g_xdbl0;
    const float* gP = br ? g_segP1 : g_segP0;
    const float* gH = br ? g_segH1 : g_segH0;
    float* ys = br ? g_ys1 : g_ys0;

    float An[NST];
    bool fast = true;
#pragma unroll
    for (int n = 0; n < NST; n++) {
        An[n] = -__expf(Alog[d * NST + n]);
        if (fabsf(An[n] + (float)(n + 1)) > 1e-3f) fast = false;
    }

    float h[NST];
#pragma unroll
    for (int n = 0; n < NST; n++) h[n] = 0.f;
    for (int t = 0; t < seg; t++) {
        const size_t o = (((size_t)b * NSEG + t) * DI + d) * NST;
        float Pt[NST], Ht[NST];
#pragma unroll
        for (int i = 0; i < 4; i++) {
            ((float4*)Pt)[i] = ((const float4*)&gP[o])[i];
            ((float4*)Ht)[i] = ((const float4*)&gH[o])[i];
        }
#pragma unroll
        for (int n = 0; n < NST; n++) h[n] = fmaf(Pt[n], h[n], Ht[n]);
    }

    const float Dd = (br ? Dr : Df)[d];
    const size_t rowbase = (size_t)b * LL + (size_t)seg * SEGL;
    const float* dp = gdelta + rowbase * DI + d;
    const float* xp = gxc + rowbase * DI + d;
    const float* bc = gxdbl + rowbase * 80 + 48;
    const float* gz = g_xz + (size_t)b * LL * 2 * DI + DI + d;  // z column

    __shared__ __align__(16) float sBC[32 * 32];

    for (int lc = 0; lc < SEGL; lc += 32) {
        __syncthreads();
        for (int i = tid; i < 32 * 32; i += 128) {
            int li = i >> 5, c = i & 31;
            sBC[i] = bc[(size_t)(lc + li) * 80 + c];
        }
        __syncthreads();
        for (int li = 0; li < 32; li++) {
            const int l = lc + li;
            const float delta = dp[(size_t)l * DI];
            const float x = xp[(size_t)l * DI];
            const float dx = delta * x;
            float bv[NST], cv[NST];
            const float4* q = (const float4*)&sBC[li * 32];
            ((float4*)bv)[0] = q[0]; ((float4*)bv)[1] = q[1];
            ((float4*)bv)[2] = q[2]; ((float4*)bv)[3] = q[3];
            ((float4*)cv)[0] = q[4]; ((float4*)cv)[1] = q[5];
            ((float4*)cv)[2] = q[6]; ((float4*)cv)[3] = q[7];
            float y = 0.f;
            if (fast) {
                const float e = __expf(-delta);
                float p = 1.f;
#pragma unroll
                for (int n = 0; n < NST; n++) {
                    p *= e;
                    h[n] = fmaf(p, h[n], dx * bv[n]);
                    y = fmaf(h[n], cv[n], y);
                }
            } else {
#pragma unroll
                for (int n = 0; n < NST; n++) {
                    float da = __expf(delta * An[n]);
                    h[n] = fmaf(da, h[n], dx * bv[n]);
                    y = fmaf(h[n], cv[n], y);
                }
            }
            const int gl = seg * SEGL + l;
            const int lo = br ? (LL - 1 - gl) : gl;  // un-flip reverse branch here
            const float zv = gz[(size_t)lo * 2 * DI];
            const float out = (y + x * Dd) * silu_f(zv);
            ys[((size_t)b * LL + lo) * DI + d] = out;
        }
    }
}

// ---------------- launch ----------------
extern "C" void kernel_launch(void* const* d_in, const int* in_sizes, int n_in,
                              void* d_out, int out_size) {
    const float* hidden     = (const float*)d_in[0];
    const float* in_proj_w  = (const float*)d_in[1];
    const float* conv_w     = (const float*)d_in[2];
    const float* conv_b     = (const float*)d_in[3];
    const float* x_proj_w   = (const float*)d_in[4];
    const float* dt_proj_w  = (const float*)d_in[5];
    const float* dt_proj_b  = (const float*)d_in[6];
    const float* A_log      = (const float*)d_in[7];
    const float* Dv         = (const float*)d_in[8];
    const float* conv_w_b   = (const float*)d_in[9];
    const float* conv_b_b   = (const float*)d_in[10];
    const float* x_proj_w_b = (const float*)d_in[11];
    const float* dt_proj_w_b= (const float*)d_in[12];
    const float* dt_proj_b_b= (const float*)d_in[13];
    const float* A_b_log    = (const float*)d_in[14];
    const float* D_b        = (const float*)d_in[15];
    const float* out_proj_w = (const float*)d_in[16];
    float* out = (float*)d_out;

    float *p_xz, *p_xc0, *p_xc1, *p_xdbl0, *p_xdbl1, *p_delta0, *p_delta1, *p_ys0, *p_ys1;
    cudaGetSymbolAddress((void**)&p_xz, g_xz);
    cudaGetSymbolAddress((void**)&p_xc0, g_xc0);
    cudaGetSymbolAddress((void**)&p_xc1, g_xc1);
    cudaGetSymbolAddress((void**)&p_xdbl0, g_xdbl0);
    cudaGetSymbolAddress((void**)&p_xdbl1, g_xdbl1);
    cudaGetSymbolAddress((void**)&p_delta0, g_delta0);
    cudaGetSymbolAddress((void**)&p_delta1, g_delta1);
    cudaGetSymbolAddress((void**)&p_ys0, g_ys0);
    cudaGetSymbolAddress((void**)&p_ys1, g_ys1);

    const int M = BB * LL;  // 2048

    // 1) xz = hidden @ in_proj_w^T   (2048 x 3072, K=768)
    {
        GArgs a{};
        a.A[0] = a.A[1] = hidden;
        a.B[0] = a.B[1] = in_proj_w;
        a.C[0] = a.C[1] = p_xz;
        a.bias[0] = a.bias[1] = nullptr;
        a.A2[0] = a.A2[1] = nullptr;
        a.M = M; a.N = 2 * DI; a.K = DM; a.lda = DM; a.ldb = DM; a.ldc = 2 * DI;
        gemm_pipe<128, 128, 16, 8, 8, 0, false><<<dim3(24, 16, 1), 256>>>(a);
    }

    // 2) depthwise causal conv + silu (both branches)
    conv_silu_k<<<(unsigned)(((size_t)BB * LL * DI + 255) / 256), 256>>>(
        conv_w, conv_b, conv_w_b, conv_b_b);

    // 3) x_dbl = xc @ x_proj_w^T   (2048 x 80, K=1536), both branches
    {
        GArgs a{};
        a.A[0] = p_xc0; a.A[1] = p_xc1;
        a.B[0] = x_proj_w; a.B[1] = x_proj_w_b;
        a.C[0] = p_xdbl0; a.C[1] = p_xdbl1;
        a.bias[0] = a.bias[1] = nullptr;
        a.A2[0] = a.A2[1] = nullptr;
        a.M = M; a.N = 80; a.K = DI; a.lda = DI; a.ldb = DI; a.ldc = 80;
        gemm_pipe<32, 80, 32, 4, 5, 0, false><<<dim3(1, 64, 2), 128>>>(a);
    }

    // 4) delta = softplus(dt @ dt_proj_w^T + bias)  (2048 x 1536, K=48), both branches
    {
        GArgs a{};
        a.A[0] = p_xdbl0; a.A[1] = p_xdbl1;
        a.B[0] = dt_proj_w; a.B[1] = dt_proj_w_b;
        a.C[0] = p_delta0; a.C[1] = p_delta1;
        a.bias[0] = dt_proj_b; a.bias[1] = dt_proj_b_b;
        a.A2[0] = a.A2[1] = nullptr;
        a.M = M; a.N = DI; a.K = DTR; a.lda = 80; a.ldb = DTR; a.ldc = DI;
        gemm_pipe<128, 128, 16, 8, 8, 1, false><<<dim3(12, 16, 2), 256>>>(a);
    }

    // 5) scan pass A (segment propagators; seg 7 not needed downstream)
    scan_passA<<<dim3(DI / 128, NSEG - 1, 4), 128>>>(A_log, A_b_log);

    // 6) scan pass C (combine + emit gated branch outputs)
    scan_passC<<<dim3(DI / 128, NSEG, 4), 128>>>(A_log, A_b_log, Dv, D_b);

    // 7) out = (ys0 + ys1) @ out_proj_w^T   (2048 x 768, K=1536); A-sum fused
    {
        GArgs a{};
        a.A[0] = a.A[1] = p_ys0;
        a.A2[0] = a.A2[1] = p_ys1;
        a.B[0] = a.B[1] = out_proj_w;
        a.C[0] = a.C[1] = out;
        a.bias[0] = a.bias[1] = nullptr;
        a.M = M; a.N = DM; a.K = DI; a.lda = DI; a.ldb = DI; a.ldc = DM;
        gemm_pipe<128, 64, 16, 8, 8, 0, true><<<dim3(12, 16, 1), 128>>>(a);
    }
}

// round 4
// speedup vs baseline: 2.8532x; 1.4033x over previous
#include <cuda_runtime.h>
#include <math.h>
#include <stdint.h>

#define DI   1536
#define DM   768
#define NST  16
#define DTR  48
#define BB   2
#define LL   1024
#define NSEG 8
#define SEGL (LL / NSEG)

// ---------------- scratch (device globals; no allocation allowed) ----------------
__device__ float g_xz[(size_t)BB * LL * 2 * DI];      // in_proj output (x | z)
__device__ float g_xc0[(size_t)BB * LL * DI];         // conv+silu fwd
__device__ float g_xc1[(size_t)BB * LL * DI];         // conv+silu rev (reversed coords)
__device__ float g_xdbl0[(size_t)BB * LL * 80];       // x_proj out fwd: [dt(48)|B(16)|C(16)]
__device__ float g_xdbl1[(size_t)BB * LL * 80];
__device__ float g_delta0[(size_t)BB * LL * DI];      // softplus(dt@W + b) fwd
__device__ float g_delta1[(size_t)BB * LL * DI];
__device__ float g_segP0[(size_t)BB * NSEG * DI * NST];
__device__ float g_segP1[(size_t)BB * NSEG * DI * NST];
__device__ float g_segH0[(size_t)BB * NSEG * DI * NST];
__device__ float g_segH1[(size_t)BB * NSEG * DI * NST];
__device__ float g_ys0[(size_t)BB * LL * DI];         // fwd branch gated output
__device__ float g_ys1[(size_t)BB * LL * DI];         // rev branch gated output (unflipped)

// =================== helpers ===================
__device__ __forceinline__ uint32_t smem_u32(const void* p) {
    uint32_t a;
    asm("{ .reg .u64 t; cvta.to.shared.u64 t, %1; cvt.u32.u64 %0, t; }" : "=r"(a) : "l"(p));
    return a;
}
#define SWZ128(x) ((x) ^ (((x) >> 3) & 0x70))

// split a float pair into bf16 hi (packed) and bf16 lo (packed); lo = bf16(a - hi)
__device__ __forceinline__ void split2(float a0, float a1, uint32_t& hi, uint32_t& lo) {
    asm("cvt.rn.bf16x2.f32 %0, %1, %2;" : "=r"(hi) : "f"(a1), "f"(a0));
    float h0 = __uint_as_float(hi << 16);
    float h1 = __uint_as_float(hi & 0xffff0000u);
    float r0 = a0 - h0, r1 = a1 - h1;
    asm("cvt.rn.bf16x2.f32 %0, %1, %2;" : "=r"(lo) : "f"(r1), "f"(r0));
}

// write one float4 as 4 bf16 hi + 4 bf16 lo into SW128-swizzled tiles
__device__ __forceinline__ void split_store(uint32_t hib, uint32_t lob, uint32_t off, float4 v) {
    uint32_t h01, l01, h23, l23;
    split2(v.x, v.y, h01, l01);
    split2(v.z, v.w, h23, l23);
    uint32_t sw = SWZ128(off);
    asm volatile("st.shared.v2.b32 [%0], {%1, %2};" :: "r"(hib + sw), "r"(h01), "r"(h23) : "memory");
    asm volatile("st.shared.v2.b32 [%0], {%1, %2};" :: "r"(lob + sw), "r"(l01), "r"(l23) : "memory");
}

#define LDSM_X4(r0, r1, r2, r3, a) \
    asm volatile("ldmatrix.sync.aligned.m8n8.x4.shared.b16 {%0,%1,%2,%3}, [%4];" \
                 : "=r"(r0), "=r"(r1), "=r"(r2), "=r"(r3) : "r"(a))
#define LDSM_X2(r0, r1, a) \
    asm volatile("ldmatrix.sync.aligned.m8n8.x2.shared.b16 {%0,%1}, [%2];" \
                 : "=r"(r0), "=r"(r1) : "r"(a))
#define MMA16816(c, a, b) \
    asm volatile("mma.sync.aligned.m16n8k16.row.col.f32.bf16.bf16.f32 " \
                 "{%0,%1,%2,%3}, {%4,%5,%6,%7}, {%8,%9}, {%0,%1,%2,%3};" \
                 : "+f"((c)[0]), "+f"((c)[1]), "+f"((c)[2]), "+f"((c)[3]) \
                 : "r"((a)[0]), "r"((a)[1]), "r"((a)[2]), "r"((a)[3]), \
                   "r"((b)[0]), "r"((b)[1]))

// =================== tensor-core NT GEMM (bf16 3-way split, mma.sync) ===================
// C[M,N] = A[M,K] @ B[N,K]^T.  Tile 128x128, k-chunk 64 (bf16), double-buffered.
// smem buffer layout (per buf, 64KB): Ahi | Alo | Bhi | Blo, each 128x64 bf16 = 16KB, SW128.
struct TCArgs {
    const float* A; const float* A2; const float* B; float* C;
    int K, lda, ldb, ldc;
};

#define MMA_SMEM (2 * 65536)

template <bool ASUM>
__global__ void __launch_bounds__(256) gemm_mma(TCArgs g) {
    extern __shared__ char smem[];
    const uint32_t sb = smem_u32(smem);
    const int tid  = threadIdx.x;
    const int wid  = tid >> 5;
    const int lane = tid & 31;
    const int wm   = wid & 3;       // warp row (32 rows of M)
    const int wn   = wid >> 2;      // warp col (64 cols of N)
    const int bm = blockIdx.y * 128;
    const int bn = blockIdx.x * 128;

    float4 ra[8], rb[8];
    float acc[2][8][4];
#pragma unroll
    for (int mt = 0; mt < 2; mt++)
#pragma unroll
        for (int nt = 0; nt < 8; nt++)
#pragma unroll
            for (int q = 0; q < 4; q++) acc[mt][nt][q] = 0.f;

    auto ldg_tile = [&](int k0) {
#pragma unroll
        for (int t = 0; t < 8; t++) {
            int i = tid + t * 256;
            int r = i >> 4, cq = i & 15;               // 128 rows x 16 float4
            size_t off = (size_t)(bm + r) * g.lda + k0 + cq * 4;
            float4 v = *(const float4*)(g.A + off);
            if (ASUM) {
                float4 w = *(const float4*)(g.A2 + off);
                v.x += w.x; v.y += w.y; v.z += w.z; v.w += w.w;
            }
            ra[t] = v;
        }
#pragma unroll
        for (int t = 0; t < 8; t++) {
            int i = tid + t * 256;
            int r = i >> 4, cq = i & 15;
            rb[t] = *(const float4*)(g.B + (size_t)(bn + r) * g.ldb + k0 + cq * 4);
        }
    };
    auto sts_tile = [&](int buf) {
        const uint32_t base = sb + buf * 65536;
#pragma unroll
        for (int t = 0; t < 8; t++) {
            int i = tid + t * 256;
            int r = i >> 4, cq = i & 15;
            split_store(base, base + 16384, (uint32_t)(r * 128 + cq * 8), ra[t]);
        }
#pragma unroll
        for (int t = 0; t < 8; t++) {
            int i = tid + t * 256;
            int r = i >> 4, cq = i & 15;
            split_store(base + 32768, base + 49152, (uint32_t)(r * 128 + cq * 8), rb[t]);
        }
    };

    // ldmatrix source addresses (within-tile byte offsets, swizzled per access)
    const int a_row = wm * 32 + (lane & 7) + ((lane >> 3) & 1) * 8;  // + mt*16
    const int a_kc8 = (lane >> 4) * 8;                                // + ks*16
    const int b_row = wn * 64 + (lane & 7);                           // + nt*8
    const int b_kc8 = ((lane >> 3) & 1) * 8;                          // + ks*16

    auto compute = [&](int buf) {
        const uint32_t ah = sb + buf * 65536;
        const uint32_t al = ah + 16384;
        const uint32_t bh = ah + 32768;
        const uint32_t bl = ah + 49152;
#pragma unroll
        for (int ks = 0; ks < 4; ks++) {
            const int k0 = ks * 16;
            uint32_t ahi[2][4], alo[2][4];
#pragma unroll
            for (int mt = 0; mt < 2; mt++) {
                uint32_t off = SWZ128((uint32_t)((a_row + mt * 16) * 128 + (k0 + a_kc8) * 2));
                LDSM_X4(ahi[mt][0], ahi[mt][1], ahi[mt][2], ahi[mt][3], ah + off);
                LDSM_X4(alo[mt][0], alo[mt][1], alo[mt][2], alo[mt][3], al + off);
            }
#pragma unroll
            for (int nt = 0; nt < 8; nt++) {
                uint32_t off = SWZ128((uint32_t)((b_row + nt * 8) * 128 + (k0 + b_kc8) * 2));
                uint32_t bhi[2], blo[2];
                LDSM_X2(bhi[0], bhi[1], bh + off);
                LDSM_X2(blo[0], blo[1], bl + off);
#pragma unroll
                for (int mt = 0; mt < 2; mt++) {
                    MMA16816(acc[mt][nt], ahi[mt], bhi);
                    MMA16816(acc[mt][nt], ahi[mt], blo);
                    MMA16816(acc[mt][nt], alo[mt], bhi);
                }
            }
        }
    };

    // -------- pipelined mainloop (one sync per k-tile) --------
    const int nk = g.K >> 6;
    ldg_tile(0);
    sts_tile(0);
    __syncthreads();
    for (int kt = 1; kt < nk; kt++) {
        ldg_tile(kt << 6);
        compute((kt - 1) & 1);
        sts_tile(kt & 1);
        __syncthreads();
    }
    compute((nk - 1) & 1);

    // -------- epilogue: mma C frag -> gmem --------
    const int er = lane >> 2;
    const int ec = (lane & 3) * 2;
#pragma unroll
    for (int mt = 0; mt < 2; mt++) {
        const int m = bm + wm * 32 + mt * 16 + er;
#pragma unroll
        for (int nt = 0; nt < 8; nt++) {
            const int n = bn + wn * 64 + nt * 8 + ec;
            *(float2*)(g.C + (size_t)m * g.ldc + n) =
                make_float2(acc[mt][nt][0], acc[mt][nt][1]);
            *(float2*)(g.C + (size_t)(m + 8) * g.ldc + n) =
                make_float2(acc[mt][nt][2], acc[mt][nt][3]);
        }
    }
}

// ---------------- pipelined SIMT NT GEMM (small GEMMs) ----------------
struct GArgs {
    const float* A[2];
    const float* A2[2];
    const float* B[2];
    float*       C[2];
    const float* bias[2];
    int M, N, K, lda, ldb, ldc;
};

template <int BM, int BN, int BK, int TM, int TN, int EPI, bool ASUM>
__global__ void __launch_bounds__((BM / TM) * (BN / TN))
gemm_pipe(GArgs g) {
    constexpr int TX = BN / TN;
    constexpr int TY = BM / TM;
    constexpr int THREADS = TX * TY;
    constexpr int PAD = 4;
    constexpr int KQ = BK / 4;
    constexpr int AV = (BM * KQ) / THREADS;
    constexpr int BV = (BN * KQ) / THREADS;

    const int br = blockIdx.z;
    const float* __restrict__ A  = g.A[br];
    const float* __restrict__ A2 = g.A2[br];
    const float* __restrict__ B  = g.B[br];
    float* __restrict__ C        = g.C[br];
    const float* __restrict__ bias = g.bias[br];

    __shared__ __align__(16) float As[2][BK][BM + PAD];
    __shared__ __align__(16) float Bs[2][BK][BN + PAD];

    const int tid = threadIdx.x;
    const int tx = tid % TX;
    const int ty = tid / TX;
    const int bm = blockIdx.y * BM;
    const int bn = blockIdx.x * BN;

    const int lda = g.lda, ldb = g.ldb;

    float4 ra[AV], rb[BV];

    auto ldg_tile = [&](int kt) {
#pragma unroll
        for (int t = 0; t < AV; t++) {
            int i = tid + t * THREADS;
            int m = i / KQ, kq = i % KQ;
            size_t off = (size_t)(bm + m) * lda + kt + kq * 4;
            float4 v = *(const float4*)(A + off);
            if (ASUM) {
                float4 w = *(const float4*)(A2 + off);
                v.x += w.x; v.y += w.y; v.z += w.z; v.w += w.w;
            }
            ra[t] = v;
        }
#pragma unroll
        for (int t = 0; t < BV; t++) {
            int i = tid + t * THREADS;
            int n = i / KQ, kq = i % KQ;
            rb[t] = *(const float4*)(B + (size_t)(bn + n) * ldb + kt + kq * 4);
        }
    };
    auto sts_tile = [&](int buf) {
#pragma unroll
        for (int t = 0; t < AV; t++) {
            int i = tid + t * THREADS;
            int m = i / KQ, kq = i % KQ;
            As[buf][kq * 4 + 0][m] = ra[t].x;
            As[buf][kq * 4 + 1][m] = ra[t].y;
            As[buf][kq * 4 + 2][m] = ra[t].z;
            As[buf][kq * 4 + 3][m] = ra[t].w;
        }
#pragma unroll
        for (int t = 0; t < BV; t++) {
            int i = tid + t * THREADS;
            int n = i / KQ, kq = i % KQ;
            Bs[buf][kq * 4 + 0][n] = rb[t].x;
            Bs[buf][kq * 4 + 1][n] = rb[t].y;
            Bs[buf][kq * 4 + 2][n] = rb[t].z;
            Bs[buf][kq * 4 + 3][n] = rb[t].w;
        }
    };

    float acc[TM][TN];
#pragma unroll
    for (int i = 0; i < TM; i++)
#pragma unroll
        for (int j = 0; j < TN; j++) acc[i][j] = 0.f;

    auto compute = [&](int buf) {
#pragma unroll
        for (int k = 0; k < BK; k++) {
            float a_frag[TM], b_frag[TN];
            if constexpr (TM % 4 == 0) {
#pragma unroll
                for (int q = 0; q < TM / 4; q++)
                    *(float4*)&a_frag[q * 4] = *(const float4*)&As[buf][k][ty * TM + q * 4];
            } else {
#pragma unroll
                for (int i = 0; i < TM; i++) a_frag[i] = As[buf][k][ty * TM + i];
            }
            if constexpr (TN % 4 == 0) {
#pragma unroll
                for (int q = 0; q < TN / 4; q++)
                    *(float4*)&b_frag[q * 4] = *(const float4*)&Bs[buf][k][tx * TN + q * 4];
            } else {
#pragma unroll
                for (int j = 0; j < TN; j++) b_frag[j] = Bs[buf][k][tx * TN + j];
            }
#pragma unroll
            for (int i = 0; i < TM; i++)
#pragma unroll
                for (int j = 0; j < TN; j++)
                    acc[i][j] = fmaf(a_frag[i], b_frag[j], acc[i][j]);
        }
    };

    const int nk = g.K / BK;
    ldg_tile(0);
    sts_tile(0);
    __syncthreads();
    for (int kt = 1; kt < nk; kt++) {
        ldg_tile(kt * BK);
        compute((kt - 1) & 1);
        sts_tile(kt & 1);
        __syncthreads();
    }
    compute((nk - 1) & 1);

#pragma unroll
    for (int i = 0; i < TM; i++) {
        const int m = bm + ty * TM + i;
#pragma unroll
        for (int j = 0; j < TN; j++) {
            const int n = bn + tx * TN + j;
            float v = acc[i][j];
            if (EPI == 1) {
                v += bias[n];
                v = (v > 20.f) ? v : log1pf(__expf(v));
            }
            C[(size_t)m * g.ldc + n] = v;
        }
    }
}

// ---------------- depthwise causal conv (K=4) + SiLU, both branches ----------------
__device__ __forceinline__ float silu_f(float v) {
    return v / (1.f + __expf(-v));
}

__global__ void __launch_bounds__(256)
conv_silu_k(const float* __restrict__ cw0, const float* __restrict__ cb0,
            const float* __restrict__ cw1, const float* __restrict__ cb1) {
    size_t idx = (size_t)blockIdx.x * 256 + threadIdx.x;
    if (idx >= (size_t)BB * LL * DI) return;
    const int d = (int)(idx % DI);
    const int l = (int)((idx / DI) % LL);
    const int b = (int)(idx / ((size_t)DI * LL));

    const float* xzb = g_xz + (size_t)b * LL * 2 * DI + d;

    float w0[4], w1[4];
#pragma unroll
    for (int k = 0; k < 4; k++) { w0[k] = cw0[d * 4 + k]; w1[k] = cw1[d * 4 + k]; }

    float s0 = cb0[d];
#pragma unroll
    for (int k = 0; k < 4; k++) {
        int ls = l - 3 + k;
        if (ls >= 0) s0 += xzb[(size_t)ls * 2 * DI] * w0[k];
    }
    g_xc0[idx] = silu_f(s0);

    float s1 = cb1[d];
#pragma unroll
    for (int k = 0; k < 4; k++) {
        if (l - 3 + k >= 0) {
            int src = LL - 1 - l + 3 - k;
            s1 += xzb[(size_t)src * 2 * DI] * w1[k];
        }
    }
    g_xc1[idx] = silu_f(s1);
}

// ---------------- selective scan, chunked (pass A: segment propagators) ----------------
__global__ void __launch_bounds__(128)
scan_passA(const float* __restrict__ AlogF, const float* __restrict__ AlogR) {
    const int tid = threadIdx.x;
    const int d = blockIdx.x * 128 + tid;
    const int seg = blockIdx.y;
    const int b = blockIdx.z & 1;
    const int br = blockIdx.z >> 1;

    const float* Alog   = br ? AlogR   : AlogF;
    const float* gdelta = br ? g_delta1 : g_delta0;
    const float* gxc    = br ? g_xc1    : g_xc0;
    const float* gxdbl  = br ? g_xdbl1  : g_xdbl0;
    float* gP = br ? g_segP1 : g_segP0;
    float* gH = br ? g_segH1 : g_segH0;

    float An[NST];
    bool fast = true;
#pragma unroll
    for (int n = 0; n < NST; n++) {
        An[n] = -__expf(Alog[d * NST + n]);
        if (fabsf(An[n] + (float)(n + 1)) > 1e-3f) fast = false;
    }

    float H[NST], P[NST];
#pragma unroll
    for (int n = 0; n < NST; n++) { H[n] = 0.f; P[n] = 1.f; }

    const size_t rowbase = (size_t)b * LL + (size_t)seg * SEGL;
    const float* dp = gdelta + rowbase * DI + d;
    const float* xp = gxc + rowbase * DI + d;
    const float* bc = gxdbl + rowbase * 80 + 48;

    __shared__ __align__(16) float sBC[32 * 32];

    for (int lc = 0; lc < SEGL; lc += 32) {
        __syncthreads();
        for (int i = tid; i < 32 * 32; i += 128) {
            int li = i >> 5, c = i & 31;
            sBC[i] = bc[(size_t)(lc + li) * 80 + c];
        }
        __syncthreads();
        for (int li = 0; li < 32; li++) {
            const int l = lc + li;
            const float delta = dp[(size_t)l * DI];
            const float x = xp[(size_t)l * DI];
            const float dx = delta * x;
            float bv[NST];
            const float4* q = (const float4*)&sBC[li * 32];
            ((float4*)bv)[0] = q[0]; ((float4*)bv)[1] = q[1];
            ((float4*)bv)[2] = q[2]; ((float4*)bv)[3] = q[3];
            if (fast) {
                const float e = __expf(-delta);
                float p = 1.f;
#pragma unroll
                for (int n = 0; n < NST; n++) {
                    p *= e;
                    H[n] = fmaf(p, H[n], dx * bv[n]);
                    P[n] *= p;
                }
            } else {
#pragma unroll
                for (int n = 0; n < NST; n++) {
                    float da = __expf(delta * An[n]);
                    H[n] = fmaf(da, H[n], dx * bv[n]);
                    P[n] *= da;
                }
            }
        }
    }

    const size_t o = (((size_t)b * NSEG + seg) * DI + d) * NST;
#pragma unroll
    for (int i = 0; i < 4; i++) {
        ((float4*)&gP[o])[i] = ((float4*)P)[i];
        ((float4*)&gH[o])[i] = ((float4*)H)[i];
    }
}

// ---------------- pass C: combine segment states, re-scan, emit gated output ----------------
__global__ void __launch_bounds__(128)
scan_passC(const float* __restrict__ AlogF, const float* __restrict__ AlogR,
           const float* __restrict__ Df, const float* __restrict__ Dr) {
    const int tid = threadIdx.x;
    const int d = blockIdx.x * 128 + tid;
    const int seg = blockIdx.y;
    const int b = blockIdx.z & 1;
    const int br = blockIdx.z >> 1;

    const float* Alog   = br ? AlogR   : AlogF;
    const float* gdelta = br ? g_delta1 : g_delta0;
    const float* gxc    = br ? g_xc1    : g_xc0;
    const float* gxdbl  = br ? g_xdbl1  : g_xdbl0;
    const float* gP = br ? g_segP1 : g_segP0;
    const float* gH = br ? g_segH1 : g_segH0;
    float* ys = br ? g_ys1 : g_ys0;

    float An[NST];
    bool fast = true;
#pragma unroll
    for (int n = 0; n < NST; n++) {
        An[n] = -__expf(Alog[d * NST + n]);
        if (fabsf(An[n] + (float)(n + 1)) > 1e-3f) fast = false;
    }

    float h[NST];
#pragma unroll
    for (int n = 0; n < NST; n++) h[n] = 0.f;
    for (int t = 0; t < seg; t++) {
        const size_t o = (((size_t)b * NSEG + t) * DI + d) * NST;
        float Pt[NST], Ht[NST];
#pragma unroll
        for (int i = 0; i < 4; i++) {
            ((float4*)Pt)[i] = ((const float4*)&gP[o])[i];
            ((float4*)Ht)[i] = ((const float4*)&gH[o])[i];
        }
#pragma unroll
        for (int n = 0; n < NST; n++) h[n] = fmaf(Pt[n], h[n], Ht[n]);
    }

    const float Dd = (br ? Dr : Df)[d];
    const size_t rowbase = (size_t)b * LL + (size_t)seg * SEGL;
    const float* dp = gdelta + rowbase * DI + d;
    const float* xp = gxc + rowbase * DI + d;
    const float* bc = gxdbl + rowbase * 80 + 48;
    const float* gz = g_xz + (size_t)b * LL * 2 * DI + DI + d;

    __shared__ __align__(16) float sBC[32 * 32];

    for (int lc = 0; lc < SEGL; lc += 32) {
        __syncthreads();
        for (int i = tid; i < 32 * 32; i += 128) {
            int li = i >> 5, c = i & 31;
            sBC[i] = bc[(size_t)(lc + li) * 80 + c];
        }
        __syncthreads();
        for (int li = 0; li < 32; li++) {
            const int l = lc + li;
            const float delta = dp[(size_t)l * DI];
            const float x = xp[(size_t)l * DI];
            const float dx = delta * x;
            float bv[NST], cv[NST];
            const float4* q = (const float4*)&sBC[li * 32];
            ((float4*)bv)[0] = q[0]; ((float4*)bv)[1] = q[1];
            ((float4*)bv)[2] = q[2]; ((float4*)bv)[3] = q[3];
            ((float4*)cv)[0] = q[4]; ((float4*)cv)[1] = q[5];
            ((float4*)cv)[2] = q[6]; ((float4*)cv)[3] = q[7];
            float y = 0.f;
            if (fast) {
                const float e = __expf(-delta);
                float p = 1.f;
#pragma unroll
                for (int n = 0; n < NST; n++) {
                    p *= e;
                    h[n] = fmaf(p, h[n], dx * bv[n]);
                    y = fmaf(h[n], cv[n], y);
                }
            } else {
#pragma unroll
                for (int n = 0; n < NST; n++) {
                    float da = __expf(delta * An[n]);
                    h[n] = fmaf(da, h[n], dx * bv[n]);
                    y = fmaf(h[n], cv[n], y);
                }
            }
            const int gl = seg * SEGL + l;
            const int lo = br ? (LL - 1 - gl) : gl;
            const float zv = gz[(size_t)lo * 2 * DI];
            const float out = (y + x * Dd) * silu_f(zv);
            ys[((size_t)b * LL + lo) * DI + d] = out;
        }
    }
}

// ---------------- launch ----------------
extern "C" void kernel_launch(void* const* d_in, const int* in_sizes, int n_in,
                              void* d_out, int out_size) {
    const float* hidden     = (const float*)d_in[0];
    const float* in_proj_w  = (const float*)d_in[1];
    const float* conv_w     = (const float*)d_in[2];
    const float* conv_b     = (const float*)d_in[3];
    const float* x_proj_w   = (const float*)d_in[4];
    const float* dt_proj_w  = (const float*)d_in[5];
    const float* dt_proj_b  = (const float*)d_in[6];
    const float* A_log      = (const float*)d_in[7];
    const float* Dv         = (const float*)d_in[8];
    const float* conv_w_b   = (const float*)d_in[9];
    const float* conv_b_b   = (const float*)d_in[10];
    const float* x_proj_w_b = (const float*)d_in[11];
    const float* dt_proj_w_b= (const float*)d_in[12];
    const float* dt_proj_b_b= (const float*)d_in[13];
    const float* A_b_log    = (const float*)d_in[14];
    const float* D_b        = (const float*)d_in[15];
    const float* out_proj_w = (const float*)d_in[16];
    float* out = (float*)d_out;

    float *p_xz, *p_xc0, *p_xc1, *p_xdbl0, *p_xdbl1, *p_delta0, *p_delta1, *p_ys0, *p_ys1;
    cudaGetSymbolAddress((void**)&p_xz, g_xz);
    cudaGetSymbolAddress((void**)&p_xc0, g_xc0);
    cudaGetSymbolAddress((void**)&p_xc1, g_xc1);
    cudaGetSymbolAddress((void**)&p_xdbl0, g_xdbl0);
    cudaGetSymbolAddress((void**)&p_xdbl1, g_xdbl1);
    cudaGetSymbolAddress((void**)&p_delta0, g_delta0);
    cudaGetSymbolAddress((void**)&p_delta1, g_delta1);
    cudaGetSymbolAddress((void**)&p_ys0, g_ys0);
    cudaGetSymbolAddress((void**)&p_ys1, g_ys1);

    cudaFuncSetAttribute(gemm_mma<false>, cudaFuncAttributeMaxDynamicSharedMemorySize, MMA_SMEM);
    cudaFuncSetAttribute(gemm_mma<true>,  cudaFuncAttributeMaxDynamicSharedMemorySize, MMA_SMEM);

    const int M = BB * LL;  // 2048

    // 1) xz = hidden @ in_proj_w^T   (2048 x 3072, K=768) — mma.sync bf16-split
    {
        TCArgs a{};
        a.A = hidden; a.A2 = nullptr; a.B = in_proj_w; a.C = p_xz;
        a.K = DM; a.lda = DM; a.ldb = DM; a.ldc = 2 * DI;
        gemm_mma<false><<<dim3(2 * DI / 128, M / 128), 256, MMA_SMEM>>>(a);
    }

    // 2) depthwise causal conv + silu (both branches)
    conv_silu_k<<<(unsigned)(((size_t)BB * LL * DI + 255) / 256), 256>>>(
        conv_w, conv_b, conv_w_b, conv_b_b);

    // 3) x_dbl = xc @ x_proj_w^T   (2048 x 80, K=1536), both branches — SIMT
    {
        GArgs a{};
        a.A[0] = p_xc0; a.A[1] = p_xc1;
        a.B[0] = x_proj_w; a.B[1] = x_proj_w_b;
        a.C[0] = p_xdbl0; a.C[1] = p_xdbl1;
        a.bias[0] = a.bias[1] = nullptr;
        a.A2[0] = a.A2[1] = nullptr;
        a.M = M; a.N = 80; a.K = DI; a.lda = DI; a.ldb = DI; a.ldc = 80;
        gemm_pipe<32, 80, 32, 4, 5, 0, false><<<dim3(1, 64, 2), 128>>>(a);
    }

    // 4) delta = softplus(dt @ dt_proj_w^T + bias)  (2048 x 1536, K=48), both branches — SIMT
    {
        GArgs a{};
        a.A[0] = p_xdbl0; a.A[1] = p_xdbl1;
        a.B[0] = dt_proj_w; a.B[1] = dt_proj_w_b;
        a.C[0] = p_delta0; a.C[1] = p_delta1;
        a.bias[0] = dt_proj_b; a.bias[1] = dt_proj_b_b;
        a.A2[0] = a.A2[1] = nullptr;
        a.M = M; a.N = DI; a.K = DTR; a.lda = 80; a.ldb = DTR; a.ldc = DI;
        gemm_pipe<128, 128, 16, 8, 8, 1, false><<<dim3(12, 16, 2), 256>>>(a);
    }

    // 5) scan pass A (segment propagators; seg 7 not needed downstream)
    scan_passA<<<dim3(DI / 128, NSEG - 1, 4), 128>>>(A_log, A_b_log);

    // 6) scan pass C (combine + emit gated branch outputs)
    scan_passC<<<dim3(DI / 128, NSEG, 4), 128>>>(A_log, A_b_log, Dv, D_b);

    // 7) out = (ys0 + ys1) @ out_proj_w^T   (2048 x 768, K=1536) — mma.sync, A-sum fused
    {
        TCArgs a{};
        a.A = p_ys0; a.A2 = p_ys1; a.B = out_proj_w; a.C = out;
        a.K = DI; a.lda = DI; a.ldb = DI; a.ldc = DM;
        gemm_mma<true><<<dim3(DM / 128, M / 128), 256, MMA_SMEM>>>(a);
    }
}

// round 5
// speedup vs baseline: 3.4611x; 1.2131x over previous
#include <cuda_runtime.h>
#include <math.h>
#include <stdint.h>

#define DI   1536
#define DM   768
#define NST  16
#define DTR  48
#define BB   2
#define LL   1024
#define NSEG 16
#define SEGL (LL / NSEG)

// ---------------- scratch (device globals; no allocation allowed) ----------------
__device__ float g_xz[(size_t)BB * LL * 2 * DI];      // in_proj output (x | z)
__device__ float g_xc0[(size_t)BB * LL * DI];         // conv+silu fwd
__device__ float g_xc1[(size_t)BB * LL * DI];         // conv+silu rev (reversed coords)
__device__ float g_xdbl0[(size_t)BB * LL * 80];       // x_proj out fwd: [dt(48)|B(16)|C(16)]
__device__ float g_xdbl1[(size_t)BB * LL * 80];
__device__ float g_delta0[(size_t)BB * LL * DI];      // softplus(dt@W + b) fwd
__device__ float g_delta1[(size_t)BB * LL * DI];
__device__ float g_segP0[(size_t)BB * NSEG * DI * NST];   // pass A: P; pass B overwrites with start-state S
__device__ float g_segP1[(size_t)BB * NSEG * DI * NST];
__device__ float g_segH0[(size_t)BB * NSEG * DI * NST];
__device__ float g_segH1[(size_t)BB * NSEG * DI * NST];
__device__ float g_ys0[(size_t)BB * LL * DI];         // fwd branch gated output
__device__ float g_ys1[(size_t)BB * LL * DI];         // rev branch gated output (unflipped)

// =================== helpers ===================
__device__ __forceinline__ uint32_t smem_u32(const void* p) {
    uint32_t a;
    asm("{ .reg .u64 t; cvta.to.shared.u64 t, %1; cvt.u32.u64 %0, t; }" : "=r"(a) : "l"(p));
    return a;
}
#define SWZ128(x) ((x) ^ (((x) >> 3) & 0x70))

// split a float pair into bf16 hi (packed) and bf16 lo (packed); lo = bf16(a - hi)
__device__ __forceinline__ void split2(float a0, float a1, uint32_t& hi, uint32_t& lo) {
    asm("cvt.rn.bf16x2.f32 %0, %1, %2;" : "=r"(hi) : "f"(a1), "f"(a0));
    float h0 = __uint_as_float(hi << 16);
    float h1 = __uint_as_float(hi & 0xffff0000u);
    float r0 = a0 - h0, r1 = a1 - h1;
    asm("cvt.rn.bf16x2.f32 %0, %1, %2;" : "=r"(lo) : "f"(r1), "f"(r0));
}

__device__ __forceinline__ void split_store(uint32_t hib, uint32_t lob, uint32_t off, float4 v) {
    uint32_t h01, l01, h23, l23;
    split2(v.x, v.y, h01, l01);
    split2(v.z, v.w, h23, l23);
    uint32_t sw = SWZ128(off);
    asm volatile("st.shared.v2.b32 [%0], {%1, %2};" :: "r"(hib + sw), "r"(h01), "r"(h23) : "memory");
    asm volatile("st.shared.v2.b32 [%0], {%1, %2};" :: "r"(lob + sw), "r"(l01), "r"(l23) : "memory");
}

#define LDSM_X4(r0, r1, r2, r3, a) \
    asm volatile("ldmatrix.sync.aligned.m8n8.x4.shared.b16 {%0,%1,%2,%3}, [%4];" \
                 : "=r"(r0), "=r"(r1), "=r"(r2), "=r"(r3) : "r"(a))
#define LDSM_X2(r0, r1, a) \
    asm volatile("ldmatrix.sync.aligned.m8n8.x2.shared.b16 {%0,%1}, [%2];" \
                 : "=r"(r0), "=r"(r1) : "r"(a))
#define MMA16816(c, a, b) \
    asm volatile("mma.sync.aligned.m16n8k16.row.col.f32.bf16.bf16.f32 " \
                 "{%0,%1,%2,%3}, {%4,%5,%6,%7}, {%8,%9}, {%0,%1,%2,%3};" \
                 : "+f"((c)[0]), "+f"((c)[1]), "+f"((c)[2]), "+f"((c)[3]) \
                 : "r"((a)[0]), "r"((a)[1]), "r"((a)[2]), "r"((a)[3]), \
                   "r"((b)[0]), "r"((b)[1]))

__device__ __forceinline__ float silu_f(float v) {
    return v / (1.f + __expf(-v));
}

// =================== big NT GEMM 128x128 (bf16 3-way split, mma.sync) ===================
struct TCArgs {
    const float* A; const float* A2; const float* B; float* C;
    int K, lda, ldb, ldc;
};

#define MMA_SMEM (2 * 65536)

template <bool ASUM>
__global__ void __launch_bounds__(256) gemm_mma(TCArgs g) {
    extern __shared__ char smem[];
    const uint32_t sb = smem_u32(smem);
    const int tid  = threadIdx.x;
    const int wid  = tid >> 5;
    const int lane = tid & 31;
    const int wm   = wid & 3;
    const int wn   = wid >> 2;
    const int bm = blockIdx.y * 128;
    const int bn = blockIdx.x * 128;

    float4 ra[8], rb[8];
    float acc[2][8][4];
#pragma unroll
    for (int mt = 0; mt < 2; mt++)
#pragma unroll
        for (int nt = 0; nt < 8; nt++)
#pragma unroll
            for (int q = 0; q < 4; q++) acc[mt][nt][q] = 0.f;

    auto ldg_tile = [&](int k0) {
#pragma unroll
        for (int t = 0; t < 8; t++) {
            int i = tid + t * 256;
            int r = i >> 4, cq = i & 15;
            size_t off = (size_t)(bm + r) * g.lda + k0 + cq * 4;
            float4 v = *(const float4*)(g.A + off);
            if (ASUM) {
                float4 w = *(const float4*)(g.A2 + off);
                v.x += w.x; v.y += w.y; v.z += w.z; v.w += w.w;
            }
            ra[t] = v;
        }
#pragma unroll
        for (int t = 0; t < 8; t++) {
            int i = tid + t * 256;
            int r = i >> 4, cq = i & 15;
            rb[t] = *(const float4*)(g.B + (size_t)(bn + r) * g.ldb + k0 + cq * 4);
        }
    };
    auto sts_tile = [&](int buf) {
        const uint32_t base = sb + buf * 65536;
#pragma unroll
        for (int t = 0; t < 8; t++) {
            int i = tid + t * 256;
            int r = i >> 4, cq = i & 15;
            split_store(base, base + 16384, (uint32_t)(r * 128 + cq * 8), ra[t]);
        }
#pragma unroll
        for (int t = 0; t < 8; t++) {
            int i = tid + t * 256;
            int r = i >> 4, cq = i & 15;
            split_store(base + 32768, base + 49152, (uint32_t)(r * 128 + cq * 8), rb[t]);
        }
    };

    const int a_row = wm * 32 + (lane & 7) + ((lane >> 3) & 1) * 8;
    const int a_kc8 = (lane >> 4) * 8;
    const int b_row = wn * 64 + (lane & 7);
    const int b_kc8 = ((lane >> 3) & 1) * 8;

    auto compute = [&](int buf) {
        const uint32_t ah = sb + buf * 65536;
        const uint32_t al = ah + 16384;
        const uint32_t bh = ah + 32768;
        const uint32_t bl = ah + 49152;
#pragma unroll
        for (int ks = 0; ks < 4; ks++) {
            const int k0 = ks * 16;
            uint32_t ahi[2][4], alo[2][4];
#pragma unroll
            for (int mt = 0; mt < 2; mt++) {
                uint32_t off = SWZ128((uint32_t)((a_row + mt * 16) * 128 + (k0 + a_kc8) * 2));
                LDSM_X4(ahi[mt][0], ahi[mt][1], ahi[mt][2], ahi[mt][3], ah + off);
                LDSM_X4(alo[mt][0], alo[mt][1], alo[mt][2], alo[mt][3], al + off);
            }
#pragma unroll
            for (int nt = 0; nt < 8; nt++) {
                uint32_t off = SWZ128((uint32_t)((b_row + nt * 8) * 128 + (k0 + b_kc8) * 2));
                uint32_t bhi[2], blo[2];
                LDSM_X2(bhi[0], bhi[1], bh + off);
                LDSM_X2(blo[0], blo[1], bl + off);
#pragma unroll
                for (int mt = 0; mt < 2; mt++) {
                    MMA16816(acc[mt][nt], ahi[mt], bhi);
                    MMA16816(acc[mt][nt], ahi[mt], blo);
                    MMA16816(acc[mt][nt], alo[mt], bhi);
                }
            }
        }
    };

    const int nk = g.K >> 6;
    ldg_tile(0);
    sts_tile(0);
    __syncthreads();
    for (int kt = 1; kt < nk; kt++) {
        ldg_tile(kt << 6);
        compute((kt - 1) & 1);
        sts_tile(kt & 1);
        __syncthreads();
    }
    compute((nk - 1) & 1);

    const int er = lane >> 2;
    const int ec = (lane & 3) * 2;
#pragma unroll
    for (int mt = 0; mt < 2; mt++) {
        const int m = bm + wm * 32 + mt * 16 + er;
#pragma unroll
        for (int nt = 0; nt < 8; nt++) {
            const int n = bn + wn * 64 + nt * 8 + ec;
            *(float2*)(g.C + (size_t)m * g.ldc + n) =
                make_float2(acc[mt][nt][0], acc[mt][nt][1]);
            *(float2*)(g.C + (size_t)(m + 8) * g.ldc + n) =
                make_float2(acc[mt][nt][2], acc[mt][nt][3]);
        }
    }
}

// =================== dt GEMM: 128x128 tile, single K-chunk of 48, softplus epilogue ===================
// C[2048,1536] = softplus(A[2048,48(lda=80)] @ B[1536,48]^T + bias)
struct G48 { const float* A[2]; const float* B[2]; float* C[2]; const float* bias[2]; };

__global__ void __launch_bounds__(256) gemm_mma48(G48 g) {
    extern __shared__ char smem[];
    const uint32_t sb = smem_u32(smem);
    const int br = blockIdx.z;
    const float* __restrict__ A = g.A[br];
    const float* __restrict__ B = g.B[br];
    float* __restrict__ C = g.C[br];
    const float* __restrict__ bias = g.bias[br];

    const int tid  = threadIdx.x;
    const int wid  = tid >> 5;
    const int lane = tid & 31;
    const int wm   = wid & 3;
    const int wn   = wid >> 2;
    const int bm = blockIdx.y * 128;
    const int bn = blockIdx.x * 128;

    const uint32_t ah = sb, al = sb + 16384, bh = sb + 32768, bl = sb + 49152;

    // A tile: rows of 48 floats (lda=80), zero-pad cols 48..63
#pragma unroll
    for (int t = 0; t < 8; t++) {
        int i = tid + t * 256;
        int r = i >> 4, cq = i & 15;
        float4 v = make_float4(0.f, 0.f, 0.f, 0.f);
        if (cq < 12) v = *(const float4*)(A + (size_t)(bm + r) * 80 + cq * 4);
        split_store(ah, al, (uint32_t)(r * 128 + cq * 8), v);
    }
#pragma unroll
    for (int t = 0; t < 8; t++) {
        int i = tid + t * 256;
        int r = i >> 4, cq = i & 15;
        float4 v = make_float4(0.f, 0.f, 0.f, 0.f);
        if (cq < 12) v = *(const float4*)(B + (size_t)(bn + r) * DTR + cq * 4);
        split_store(bh, bl, (uint32_t)(r * 128 + cq * 8), v);
    }
    __syncthreads();

    float acc[2][8][4];
#pragma unroll
    for (int mt = 0; mt < 2; mt++)
#pragma unroll
        for (int nt = 0; nt < 8; nt++)
#pragma unroll
            for (int q = 0; q < 4; q++) acc[mt][nt][q] = 0.f;

    const int a_row = wm * 32 + (lane & 7) + ((lane >> 3) & 1) * 8;
    const int a_kc8 = (lane >> 4) * 8;
    const int b_row = wn * 64 + (lane & 7);
    const int b_kc8 = ((lane >> 3) & 1) * 8;

#pragma unroll
    for (int ks = 0; ks < 3; ks++) {   // K = 48 = 3 x 16
        const int k0 = ks * 16;
        uint32_t ahi[2][4], alo[2][4];
#pragma unroll
        for (int mt = 0; mt < 2; mt++) {
            uint32_t off = SWZ128((uint32_t)((a_row + mt * 16) * 128 + (k0 + a_kc8) * 2));
            LDSM_X4(ahi[mt][0], ahi[mt][1], ahi[mt][2], ahi[mt][3], ah + off);
            LDSM_X4(alo[mt][0], alo[mt][1], alo[mt][2], alo[mt][3], al + off);
        }
#pragma unroll
        for (int nt = 0; nt < 8; nt++) {
            uint32_t off = SWZ128((uint32_t)((b_row + nt * 8) * 128 + (k0 + b_kc8) * 2));
            uint32_t bhi[2], blo[2];
            LDSM_X2(bhi[0], bhi[1], bh + off);
            LDSM_X2(blo[0], blo[1], bl + off);
#pragma unroll
            for (int mt = 0; mt < 2; mt++) {
                MMA16816(acc[mt][nt], ahi[mt], bhi);
                MMA16816(acc[mt][nt], ahi[mt], blo);
                MMA16816(acc[mt][nt], alo[mt], bhi);
            }
        }
    }

    const int er = lane >> 2;
    const int ec = (lane & 3) * 2;
#pragma unroll
    for (int mt = 0; mt < 2; mt++) {
        const int m = bm + wm * 32 + mt * 16 + er;
#pragma unroll
        for (int nt = 0; nt < 8; nt++) {
            const int n = bn + wn * 64 + nt * 8 + ec;
            const float b0 = bias[n], b1 = bias[n + 1];
            float v0 = acc[mt][nt][0] + b0, v1 = acc[mt][nt][1] + b1;
            float v2 = acc[mt][nt][2] + b0, v3 = acc[mt][nt][3] + b1;
            v0 = (v0 > 20.f) ? v0 : log1pf(__expf(v0));
            v1 = (v1 > 20.f) ? v1 : log1pf(__expf(v1));
            v2 = (v2 > 20.f) ? v2 : log1pf(__expf(v2));
            v3 = (v3 > 20.f) ? v3 : log1pf(__expf(v3));
            *(float2*)(C + (size_t)m * DI + n) = make_float2(v0, v1);
            *(float2*)(C + (size_t)(m + 8) * DI + n) = make_float2(v2, v3);
        }
    }
}

// =================== x_proj GEMM: 128x80 tile, K=1536 pipelined ===================
// C[2048,80] = A[2048,1536] @ B[80,1536]^T
struct G80 { const float* A[2]; const float* B[2]; float* C[2]; };

// per buf: Ahi 16K | Alo 16K | Bhi 10K | Blo 10K  = 52KB; x2 bufs
#define MMA80_BUF 53248
#define MMA80_SMEM (2 * MMA80_BUF)

__global__ void __launch_bounds__(256) gemm_mma80(G80 g) {
    extern __shared__ char smem[];
    const uint32_t sb = smem_u32(smem);
    const int br = blockIdx.z;
    const float* __restrict__ A = g.A[br];
    const float* __restrict__ B = g.B[br];
    float* __restrict__ C = g.C[br];

    const int tid  = threadIdx.x;
    const int wid  = tid >> 5;
    const int lane = tid & 31;
    const int wm   = wid & 3;       // 32 rows
    const int wn   = wid >> 2;      // 40 cols
    const int bm = blockIdx.y * 128;

    float4 ra[8], rb[5];
    float acc[2][5][4];
#pragma unroll
    for (int mt = 0; mt < 2; mt++)
#pragma unroll
        for (int nt = 0; nt < 5; nt++)
#pragma unroll
            for (int q = 0; q < 4; q++) acc[mt][nt][q] = 0.f;

    auto ldg_tile = [&](int k0) {
#pragma unroll
        for (int t = 0; t < 8; t++) {
            int i = tid + t * 256;
            int r = i >> 4, cq = i & 15;
            ra[t] = *(const float4*)(A + (size_t)(bm + r) * DI + k0 + cq * 4);
        }
#pragma unroll
        for (int t = 0; t < 5; t++) {
            int i = tid + t * 256;      // 1280 = 80 rows x 16 float4
            int r = i >> 4, cq = i & 15;
            rb[t] = *(const float4*)(B + (size_t)r * DI + k0 + cq * 4);
        }
    };
    auto sts_tile = [&](int buf) {
        const uint32_t base = sb + buf * MMA80_BUF;
#pragma unroll
        for (int t = 0; t < 8; t++) {
            int i = tid + t * 256;
            int r = i >> 4, cq = i & 15;
            split_store(base, base + 16384, (uint32_t)(r * 128 + cq * 8), ra[t]);
        }
#pragma unroll
        for (int t = 0; t < 5; t++) {
            int i = tid + t * 256;
            int r = i >> 4, cq = i & 15;
            split_store(base + 32768, base + 43008, (uint32_t)(r * 128 + cq * 8), rb[t]);
        }
    };

    const int a_row = wm * 32 + (lane & 7) + ((lane >> 3) & 1) * 8;
    const int a_kc8 = (lane >> 4) * 8;
    const int b_row = wn * 40 + (lane & 7);
    const int b_kc8 = ((lane >> 3) & 1) * 8;

    auto compute = [&](int buf) {
        const uint32_t ah = sb + buf * MMA80_BUF;
        const uint32_t al = ah + 16384;
        const uint32_t bh = ah + 32768;
        const uint32_t bl = ah + 43008;
#pragma unroll
        for (int ks = 0; ks < 4; ks++) {
            const int k0 = ks * 16;
            uint32_t ahi[2][4], alo[2][4];
#pragma unroll
            for (int mt = 0; mt < 2; mt++) {
                uint32_t off = SWZ128((uint32_t)((a_row + mt * 16) * 128 + (k0 + a_kc8) * 2));
                LDSM_X4(ahi[mt][0], ahi[mt][1], ahi[mt][2], ahi[mt][3], ah + off);
                LDSM_X4(alo[mt][0], alo[mt][1], alo[mt][2], alo[mt][3], al + off);
            }
#pragma unroll
            for (int nt = 0; nt < 5; nt++) {
                uint32_t off = SWZ128((uint32_t)((b_row + nt * 8) * 128 + (k0 + b_kc8) * 2));
                uint32_t bhi[2], blo[2];
                LDSM_X2(bhi[0], bhi[1], bh + off);
                LDSM_X2(blo[0], blo[1], bl + off);
#pragma unroll
                for (int mt = 0; mt < 2; mt++) {
                    MMA16816(acc[mt][nt], ahi[mt], bhi);
                    MMA16816(acc[mt][nt], ahi[mt], blo);
                    MMA16816(acc[mt][nt], alo[mt], bhi);
                }
            }
        }
    };

    const int nk = DI >> 6;  // 24
    ldg_tile(0);
    sts_tile(0);
    __syncthreads();
    for (int kt = 1; kt < nk; kt++) {
        ldg_tile(kt << 6);
        compute((kt - 1) & 1);
        sts_tile(kt & 1);
        __syncthreads();
    }
    compute((nk - 1) & 1);

    const int er = lane >> 2;
    const int ec = (lane & 3) * 2;
#pragma unroll
    for (int mt = 0; mt < 2; mt++) {
        const int m = bm + wm * 32 + mt * 16 + er;
#pragma unroll
        for (int nt = 0; nt < 5; nt++) {
            const int n = wn * 40 + nt * 8 + ec;
            *(float2*)(C + (size_t)m * 80 + n) =
                make_float2(acc[mt][nt][0], acc[mt][nt][1]);
            *(float2*)(C + (size_t)(m + 8) * 80 + n) =
                make_float2(acc[mt][nt][2], acc[mt][nt][3]);
        }
    }
}

// ---------------- depthwise causal conv (K=4) + SiLU, float4 over channels ----------------
__global__ void __launch_bounds__(256)
conv_silu_k(const float* __restrict__ cw0, const float* __restrict__ cb0,
            const float* __restrict__ cw1, const float* __restrict__ cb1) {
    const size_t idx4 = (size_t)blockIdx.x * 256 + threadIdx.x;
    const int D4 = DI / 4;
    if (idx4 >= (size_t)BB * LL * D4) return;
    const int dq = (int)(idx4 % D4);
    const int l  = (int)((idx4 / D4) % LL);
    const int b  = (int)(idx4 / ((size_t)D4 * LL));
    const int d  = dq * 4;

    const float* xzb = g_xz + (size_t)b * LL * 2 * DI + d;

    float w0[4][4], w1[4][4];
#pragma unroll
    for (int j = 0; j < 4; j++) {
        float4 a = *(const float4*)(cw0 + (d + j) * 4);
        w0[j][0] = a.x; w0[j][1] = a.y; w0[j][2] = a.z; w0[j][3] = a.w;
        float4 c = *(const float4*)(cw1 + (d + j) * 4);
        w1[j][0] = c.x; w1[j][1] = c.y; w1[j][2] = c.z; w1[j][3] = c.w;
    }

    float s0[4], s1[4];
    {
        float4 b0 = *(const float4*)(cb0 + d);
        float4 b1 = *(const float4*)(cb1 + d);
        s0[0] = b0.x; s0[1] = b0.y; s0[2] = b0.z; s0[3] = b0.w;
        s1[0] = b1.x; s1[1] = b1.y; s1[2] = b1.z; s1[3] = b1.w;
    }

#pragma unroll
    for (int k = 0; k < 4; k++) {
        const int ls = l - 3 + k;
        if (ls >= 0) {
            float4 xv = *(const float4*)(xzb + (size_t)ls * 2 * DI);
            s0[0] += xv.x * w0[0][k]; s0[1] += xv.y * w0[1][k];
            s0[2] += xv.z * w0[2][k]; s0[3] += xv.w * w0[3][k];
            const int src = LL - 1 - l + 3 - k;
            float4 yv = *(const float4*)(xzb + (size_t)src * 2 * DI);
            s1[0] += yv.x * w1[0][k]; s1[1] += yv.y * w1[1][k];
            s1[2] += yv.z * w1[2][k]; s1[3] += yv.w * w1[3][k];
        }
    }

    float4 o0 = make_float4(silu_f(s0[0]), silu_f(s0[1]), silu_f(s0[2]), silu_f(s0[3]));
    float4 o1 = make_float4(silu_f(s1[0]), silu_f(s1[1]), silu_f(s1[2]), silu_f(s1[3]));
    const size_t o = ((size_t)b * LL + l) * DI + d;
    *(float4*)(g_xc0 + o) = o0;
    *(float4*)(g_xc1 + o) = o1;
}

// ---------------- selective scan pass A: per-segment propagators ----------------
__global__ void __launch_bounds__(128)
scan_passA(const float* __restrict__ AlogF, const float* __restrict__ AlogR) {
    const int tid = threadIdx.x;
    const int d = blockIdx.x * 128 + tid;
    const int seg = blockIdx.y;
    const int b = blockIdx.z & 1;
    const int br = blockIdx.z >> 1;

    const float* Alog   = br ? AlogR   : AlogF;
    const float* gdelta = br ? g_delta1 : g_delta0;
    const float* gxc    = br ? g_xc1    : g_xc0;
    const float* gxdbl  = br ? g_xdbl1  : g_xdbl0;
    float* gP = br ? g_segP1 : g_segP0;
    float* gH = br ? g_segH1 : g_segH0;

    float An[NST];
    bool fast = true;
#pragma unroll
    for (int n = 0; n < NST; n++) {
        An[n] = -__expf(Alog[d * NST + n]);
        if (fabsf(An[n] + (float)(n + 1)) > 1e-3f) fast = false;
    }

    float H[NST], P[NST];
#pragma unroll
    for (int n = 0; n < NST; n++) { H[n] = 0.f; P[n] = 1.f; }

    const size_t rowbase = (size_t)b * LL + (size_t)seg * SEGL;
    const float* dp = gdelta + rowbase * DI + d;
    const float* xp = gxc + rowbase * DI + d;
    const float* bc = gxdbl + rowbase * 80 + 48;

    __shared__ __align__(16) float sBC[32 * 32];

    for (int lc = 0; lc < SEGL; lc += 32) {
        __syncthreads();
        for (int i = tid; i < 32 * 32; i += 128) {
            int li = i >> 5, c = i & 31;
            sBC[i] = bc[(size_t)(lc + li) * 80 + c];
        }
        __syncthreads();
        for (int li = 0; li < 32; li++) {
            const int l = lc + li;
            const float delta = dp[(size_t)l * DI];
            const float x = xp[(size_t)l * DI];
            const float dx = delta * x;
            float bv[NST];
            const float4* q = (const float4*)&sBC[li * 32];
            ((float4*)bv)[0] = q[0]; ((float4*)bv)[1] = q[1];
            ((float4*)bv)[2] = q[2]; ((float4*)bv)[3] = q[3];
            if (fast) {
                const float e = __expf(-delta);
                float p = 1.f;
#pragma unroll
                for (int n = 0; n < NST; n++) {
                    p *= e;
                    H[n] = fmaf(p, H[n], dx * bv[n]);
                    P[n] *= p;
                }
            } else {
#pragma unroll
                for (int n = 0; n < NST; n++) {
                    float da = __expf(delta * An[n]);
                    H[n] = fmaf(da, H[n], dx * bv[n]);
                    P[n] *= da;
                }
            }
        }
    }

    const size_t o = (((size_t)b * NSEG + seg) * DI + d) * NST;
#pragma unroll
    for (int i = 0; i < 4; i++) {
        ((float4*)&gP[o])[i] = ((float4*)P)[i];
        ((float4*)&gH[o])[i] = ((float4*)H)[i];
    }
}

// ---------------- pass B: sequential combine -> per-segment start states (in place over P) ----------------
__global__ void __launch_bounds__(128)
scan_passB() {
    const int idx = blockIdx.x * 128 + threadIdx.x;   // 0 .. 2*2*1536-1
    const int d = idx % DI;
    const int rest = idx / DI;
    const int b = rest & 1;
    const int br = rest >> 1;
    float* gP = br ? g_segP1 : g_segP0;
    const float* gH = br ? g_segH1 : g_segH0;

    float h[NST];
#pragma unroll
    for (int n = 0; n < NST; n++) h[n] = 0.f;

    for (int t = 0; t < NSEG; t++) {
        const size_t o = (((size_t)b * NSEG + t) * DI + d) * NST;
        float Pt[NST], Ht[NST];
        if (t < NSEG - 1) {
#pragma unroll
            for (int i = 0; i < 4; i++) {
                ((float4*)Pt)[i] = ((const float4*)&gP[o])[i];
                ((float4*)Ht)[i] = ((const float4*)&gH[o])[i];
            }
        }
        // overwrite P[t] with start state S[t]
#pragma unroll
        for (int i = 0; i < 4; i++) ((float4*)&gP[o])[i] = ((float4*)h)[i];
        if (t < NSEG - 1) {
#pragma unroll
            for (int n = 0; n < NST; n++) h[n] = fmaf(Pt[n], h[n], Ht[n]);
        }
    }
}

// ---------------- pass C: re-scan from start state, emit gated output ----------------
__global__ void __launch_bounds__(128)
scan_passC(const float* __restrict__ AlogF, const float* __restrict__ AlogR,
           const float* __restrict__ Df, const float* __restrict__ Dr) {
    const int tid = threadIdx.x;
    const int d = blockIdx.x * 128 + tid;
    const int seg = blockIdx.y;
    const int b = blockIdx.z & 1;
    const int br = blockIdx.z >> 1;

    const float* Alog   = br ? AlogR   : AlogF;
    const float* gdelta = br ? g_delta1 : g_delta0;
    const float* gxc    = br ? g_xc1    : g_xc0;
    const float* gxdbl  = br ? g_xdbl1  : g_xdbl0;
    const float* gS = br ? g_segP1 : g_segP0;   // start states (written by pass B)
    float* ys = br ? g_ys1 : g_ys0;

    float An[NST];
    bool fast = true;
#pragma unroll
    for (int n = 0; n < NST; n++) {
        An[n] = -__expf(Alog[d * NST + n]);
        if (fabsf(An[n] + (float)(n + 1)) > 1e-3f) fast = false;
    }

    float h[NST];
    {
        const size_t o = (((size_t)b * NSEG + seg) * DI + d) * NST;
#pragma unroll
        for (int i = 0; i < 4; i++) ((float4*)h)[i] = ((const float4*)&gS[o])[i];
    }

    const float Dd = (br ? Dr : Df)[d];
    const size_t rowbase = (size_t)b * LL + (size_t)seg * SEGL;
    const float* dp = gdelta + rowbase * DI + d;
    const float* xp = gxc + rowbase * DI + d;
    const float* bc = gxdbl + rowbase * 80 + 48;
    const float* gz = g_xz + (size_t)b * LL * 2 * DI + DI + d;

    __shared__ __align__(16) float sBC[32 * 32];

    for (int lc = 0; lc < SEGL; lc += 32) {
        __syncthreads();
        for (int i = tid; i < 32 * 32; i += 128) {
            int li = i >> 5, c = i & 31;
            sBC[i] = bc[(size_t)(lc + li) * 80 + c];
        }
        __syncthreads();
        for (int li = 0; li < 32; li++) {
            const int l = lc + li;
            const float delta = dp[(size_t)l * DI];
            const float x = xp[(size_t)l * DI];
            const float dx = delta * x;
            float bv[NST], cv[NST];
            const float4* q = (const float4*)&sBC[li * 32];
            ((float4*)bv)[0] = q[0]; ((float4*)bv)[1] = q[1];
            ((float4*)bv)[2] = q[2]; ((float4*)bv)[3] = q[3];
            ((float4*)cv)[0] = q[4]; ((float4*)cv)[1] = q[5];
            ((float4*)cv)[2] = q[6]; ((float4*)cv)[3] = q[7];
            float y = 0.f;
            if (fast) {
                const float e = __expf(-delta);
                float p = 1.f;
#pragma unroll
                for (int n = 0; n < NST; n++) {
                    p *= e;
                    h[n] = fmaf(p, h[n], dx * bv[n]);
                    y = fmaf(h[n], cv[n], y);
                }
            } else {
#pragma unroll
                for (int n = 0; n < NST; n++) {
                    float da = __expf(delta * An[n]);
                    h[n] = fmaf(da, h[n], dx * bv[n]);
                    y = fmaf(h[n], cv[n], y);
                }
            }
            const int gl = seg * SEGL + l;
            const int lo = br ? (LL - 1 - gl) : gl;
            const float zv = gz[(size_t)lo * 2 * DI];
            const float out = (y + x * Dd) * silu_f(zv);
            ys[((size_t)b * LL + lo) * DI + d] = out;
        }
    }
}

// ---------------- launch ----------------
extern "C" void kernel_launch(void* const* d_in, const int* in_sizes, int n_in,
                              void* d_out, int out_size) {
    const float* hidden     = (const float*)d_in[0];
    const float* in_proj_w  = (const float*)d_in[1];
    const float* conv_w     = (const float*)d_in[2];
    const float* conv_b     = (const float*)d_in[3];
    const float* x_proj_w   = (const float*)d_in[4];
    const float* dt_proj_w  = (const float*)d_in[5];
    const float* dt_proj_b  = (const float*)d_in[6];
    const float* A_log      = (const float*)d_in[7];
    const float* Dv         = (const float*)d_in[8];
    const float* conv_w_b   = (const float*)d_in[9];
    const float* conv_b_b   = (const float*)d_in[10];
    const float* x_proj_w_b = (const float*)d_in[11];
    const float* dt_proj_w_b= (const float*)d_in[12];
    const float* dt_proj_b_b= (const float*)d_in[13];
    const float* A_b_log    = (const float*)d_in[14];
    const float* D_b        = (const float*)d_in[15];
    const float* out_proj_w = (const float*)d_in[16];
    float* out = (float*)d_out;

    float *p_xz, *p_xc0, *p_xc1, *p_xdbl0, *p_xdbl1, *p_delta0, *p_delta1, *p_ys0, *p_ys1;
    cudaGetSymbolAddress((void**)&p_xz, g_xz);
    cudaGetSymbolAddress((void**)&p_xc0, g_xc0);
    cudaGetSymbolAddress((void**)&p_xc1, g_xc1);
    cudaGetSymbolAddress((void**)&p_xdbl0, g_xdbl0);
    cudaGetSymbolAddress((void**)&p_xdbl1, g_xdbl1);
    cudaGetSymbolAddress((void**)&p_delta0, g_delta0);
    cudaGetSymbolAddress((void**)&p_delta1, g_delta1);
    cudaGetSymbolAddress((void**)&p_ys0, g_ys0);
    cudaGetSymbolAddress((void**)&p_ys1, g_ys1);

    cudaFuncSetAttribute(gemm_mma<false>, cudaFuncAttributeMaxDynamicSharedMemorySize, MMA_SMEM);
    cudaFuncSetAttribute(gemm_mma<true>,  cudaFuncAttributeMaxDynamicSharedMemorySize, MMA_SMEM);
    cudaFuncSetAttribute(gemm_mma48, cudaFuncAttributeMaxDynamicSharedMemorySize, 65536);
    cudaFuncSetAttribute(gemm_mma80, cudaFuncAttributeMaxDynamicSharedMemorySize, MMA80_SMEM);

    const int M = BB * LL;  // 2048

    // 1) xz = hidden @ in_proj_w^T
    {
        TCArgs a{};
        a.A = hidden; a.A2 = nullptr; a.B = in_proj_w; a.C = p_xz;
        a.K = DM; a.lda = DM; a.ldb = DM; a.ldc = 2 * DI;
        gemm_mma<false><<<dim3(2 * DI / 128, M / 128), 256, MMA_SMEM>>>(a);
    }

    // 2) depthwise causal conv + silu (both branches), float4
    conv_silu_k<<<(unsigned)(((size_t)BB * LL * (DI / 4) + 255) / 256), 256>>>(
        conv_w, conv_b, conv_w_b, conv_b_b);

    // 3) x_dbl = xc @ x_proj_w^T  (mma, both branches)
    {
        G80 a{};
        a.A[0] = p_xc0; a.A[1] = p_xc1;
        a.B[0] = x_proj_w; a.B[1] = x_proj_w_b;
        a.C[0] = p_xdbl0; a.C[1] = p_xdbl1;
        gemm_mma80<<<dim3(1, M / 128, 2), 256, MMA80_SMEM>>>(a);
    }

    // 4) delta = softplus(dt @ dt_proj_w^T + bias)  (mma, both branches)
    {
        G48 a{};
        a.A[0] = p_xdbl0; a.A[1] = p_xdbl1;
        a.B[0] = dt_proj_w; a.B[1] = dt_proj_w_b;
        a.C[0] = p_delta0; a.C[1] = p_delta1;
        a.bias[0] = dt_proj_b; a.bias[1] = dt_proj_b_b;
        gemm_mma48<<<dim3(DI / 128, M / 128, 2), 256, 65536>>>(a);
    }

    // 5) scan pass A (segments 0..NSEG-2)
    scan_passA<<<dim3(DI / 128, NSEG - 1, 4), 128>>>(A_log, A_b_log);

    // 6) pass B: turn (P,H) into per-segment start states
    scan_passB<<<(BB * 2 * DI) / 128, 128>>>();

    // 7) pass C: re-scan + gated output
    scan_passC<<<dim3(DI / 128, NSEG, 4), 128>>>(A_log, A_b_log, Dv, D_b);

    // 8) out = (ys0 + ys1) @ out_proj_w^T  (mma, A-sum fused)
    {
        TCArgs a{};
        a.A = p_ys0; a.A2 = p_ys1; a.B = out_proj_w; a.C = out;
        a.K = DI; a.lda = DI; a.ldb = DI; a.ldc = DM;
        gemm_mma<true><<<dim3(DM / 128, M / 128), 256, MMA_SMEM>>>(a);
    }
}

// round 6
// speedup vs baseline: 4.0492x; 1.1699x over previous
#include <cuda_runtime.h>
#include <math.h>
#include <stdint.h>

#define DI   1536
#define DM   768
#define NST  16
#define DTR  48
#define BB   2
#define LL   1024
#define NSEG 16
#define SEGL (LL / NSEG)

// ---------------- scratch (device globals; no allocation allowed) ----------------
__device__ float g_xz[(size_t)BB * LL * 2 * DI];      // in_proj output (x | z)
__device__ float g_xc0[(size_t)BB * LL * DI];         // conv+silu fwd (f32, for scans)
__device__ float g_xc1[(size_t)BB * LL * DI];
__device__ float g_xdbl0[(size_t)BB * LL * 80];       // x_proj out (summed): [dt|B|C]
__device__ float g_xdbl1[(size_t)BB * LL * 80];
__device__ float g_delta0[(size_t)BB * LL * DI];
__device__ float g_delta1[(size_t)BB * LL * DI];
__device__ float g_segP0[(size_t)BB * NSEG * DI * NST];
__device__ float g_segP1[(size_t)BB * NSEG * DI * NST];
__device__ float g_segH0[(size_t)BB * NSEG * DI * NST];
__device__ float g_segH1[(size_t)BB * NSEG * DI * NST];
__device__ float g_ys0[(size_t)BB * LL * DI];
__device__ float g_ys1[(size_t)BB * LL * DI];
__device__ float g_xdblp[(size_t)4 * BB * LL * 80];   // x_proj partials [br*2+kh]

// bf16 hi/lo pre-split buffers
__device__ uint16_t g_hidh[(size_t)BB * LL * DM],     g_hidl[(size_t)BB * LL * DM];
__device__ uint16_t g_w1h[(size_t)2 * DI * DM],       g_w1l[(size_t)2 * DI * DM];
__device__ uint16_t g_xc0h[(size_t)BB * LL * DI],     g_xc0l[(size_t)BB * LL * DI];
__device__ uint16_t g_xc1h[(size_t)BB * LL * DI],     g_xc1l[(size_t)BB * LL * DI];
__device__ uint16_t g_xwh[(size_t)2 * 80 * DI],       g_xwl[(size_t)2 * 80 * DI];
__device__ uint16_t g_dtwh[(size_t)2 * DI * DTR],     g_dtwl[(size_t)2 * DI * DTR];
__device__ uint16_t g_owh[(size_t)DM * DI],           g_owl[(size_t)DM * DI];
__device__ uint16_t g_xdh[(size_t)2 * BB * LL * 80],  g_xdl[(size_t)2 * BB * LL * 80];
__device__ uint16_t g_ysh[(size_t)BB * LL * DI],      g_ysl[(size_t)BB * LL * DI];

// =================== helpers ===================
__device__ __forceinline__ uint32_t smem_u32(const void* p) {
    uint32_t a;
    asm("{ .reg .u64 t; cvta.to.shared.u64 t, %1; cvt.u32.u64 %0, t; }" : "=r"(a) : "l"(p));
    return a;
}
#define SWZ128(x) ((x) ^ (((x) >> 3) & 0x70))

__device__ __forceinline__ void split2(float a0, float a1, uint32_t& hi, uint32_t& lo) {
    asm("cvt.rn.bf16x2.f32 %0, %1, %2;" : "=r"(hi) : "f"(a1), "f"(a0));
    float h0 = __uint_as_float(hi << 16);
    float h1 = __uint_as_float(hi & 0xffff0000u);
    float r0 = a0 - h0, r1 = a1 - h1;
    asm("cvt.rn.bf16x2.f32 %0, %1, %2;" : "=r"(lo) : "f"(r1), "f"(r0));
}

// split float4 -> 4 bf16 hi + 4 bf16 lo, write to global uint16 arrays at element j
__device__ __forceinline__ void split_g(uint16_t* hi, uint16_t* lo, size_t j, float4 v) {
    uint32_t h01, l01, h23, l23;
    split2(v.x, v.y, h01, l01);
    split2(v.z, v.w, h23, l23);
    *(uint2*)(hi + j) = make_uint2(h01, h23);
    *(uint2*)(lo + j) = make_uint2(l01, l23);
}

#define LDSM_X4(r0, r1, r2, r3, a) \
    asm volatile("ldmatrix.sync.aligned.m8n8.x4.shared.b16 {%0,%1,%2,%3}, [%4];" \
                 : "=r"(r0), "=r"(r1), "=r"(r2), "=r"(r3) : "r"(a))
#define LDSM_X2(r0, r1, a) \
    asm volatile("ldmatrix.sync.aligned.m8n8.x2.shared.b16 {%0,%1}, [%2];" \
                 : "=r"(r0), "=r"(r1) : "r"(a))
#define MMA16816(c, a, b) \
    asm volatile("mma.sync.aligned.m16n8k16.row.col.f32.bf16.bf16.f32 " \
                 "{%0,%1,%2,%3}, {%4,%5,%6,%7}, {%8,%9}, {%0,%1,%2,%3};" \
                 : "+f"((c)[0]), "+f"((c)[1]), "+f"((c)[2]), "+f"((c)[3]) \
                 : "r"((a)[0]), "r"((a)[1]), "r"((a)[2]), "r"((a)[3]), \
                   "r"((b)[0]), "r"((b)[1]))
#define STS128U(addr, v) \
    asm volatile("st.shared.v4.b32 [%0], {%1,%2,%3,%4};" \
                 :: "r"(addr), "r"((v).x), "r"((v).y), "r"((v).z), "r"((v).w) : "memory")

__device__ __forceinline__ float silu_f(float v) {
    return v / (1.f + __expf(-v));
}
__device__ __forceinline__ float softplus_f(float v) {
    return fmaxf(v, 0.f) + __logf(1.f + __expf(-fabsf(v)));
}

// =================== split_many: pre-split static tensors ===================
struct SSeg { const float* src; uint16_t* hi; uint16_t* lo; int base4; int n4; };
struct SArgs { SSeg s[7]; int total4; };

__global__ void __launch_bounds__(256) split_many(SArgs a) {
    int idx = blockIdx.x * 256 + threadIdx.x;
    if (idx >= a.total4) return;
#pragma unroll
    for (int k = 0; k < 7; k++) {
        int j = idx - a.s[k].base4;
        if (j >= 0 && j < a.s[k].n4) {
            float4 v = *(const float4*)(a.s[k].src + (size_t)j * 4);
            split_g(a.s[k].hi, a.s[k].lo, (size_t)j * 4, v);
            return;
        }
    }
}

// =================== big NT GEMM 128x128 (bf16 pre-split, mma.sync) ===================
struct TBArgs {
    const uint16_t* Ah; const uint16_t* Al;
    const uint16_t* Bh; const uint16_t* Bl;
    float* C; int K, lda, ldb, ldc;
};

#define MMA_SMEM (2 * 65536)

__global__ void __launch_bounds__(256) gemm_mma_b(TBArgs g) {
    extern __shared__ char smem[];
    const uint32_t sb = smem_u32(smem);
    const int tid  = threadIdx.x;
    const int wid  = tid >> 5;
    const int lane = tid & 31;
    const int wm   = wid & 3;
    const int wn   = wid >> 2;
    const int bm = blockIdx.y * 128;
    const int bn = blockIdx.x * 128;

    uint4 rah[4], ral[4], rbh[4], rbl[4];
    float acc[2][8][4];
#pragma unroll
    for (int mt = 0; mt < 2; mt++)
#pragma unroll
        for (int nt = 0; nt < 8; nt++)
#pragma unroll
            for (int q = 0; q < 4; q++) acc[mt][nt][q] = 0.f;

    auto ldg_tile = [&](int k0) {
#pragma unroll
        for (int t = 0; t < 4; t++) {
            int i = tid + t * 256;
            int r = i >> 3, q = i & 7;
            size_t ao = (size_t)(bm + r) * g.lda + k0 + q * 8;
            rah[t] = *(const uint4*)(g.Ah + ao);
            ral[t] = *(const uint4*)(g.Al + ao);
            size_t bo = (size_t)(bn + r) * g.ldb + k0 + q * 8;
            rbh[t] = *(const uint4*)(g.Bh + bo);
            rbl[t] = *(const uint4*)(g.Bl + bo);
        }
    };
    auto sts_tile = [&](int buf) {
        const uint32_t base = sb + buf * 65536;
#pragma unroll
        for (int t = 0; t < 4; t++) {
            int i = tid + t * 256;
            int r = i >> 3, q = i & 7;
            uint32_t off = SWZ128((uint32_t)(r * 128 + q * 16));
            STS128U(base + off, rah[t]);
            STS128U(base + 16384 + off, ral[t]);
            STS128U(base + 32768 + off, rbh[t]);
            STS128U(base + 49152 + off, rbl[t]);
        }
    };

    const int a_row = wm * 32 + (lane & 7) + ((lane >> 3) & 1) * 8;
    const int a_kc8 = (lane >> 4) * 8;
    const int b_row = wn * 64 + (lane & 7);
    const int b_kc8 = ((lane >> 3) & 1) * 8;

    auto compute = [&](int buf) {
        const uint32_t ah = sb + buf * 65536;
        const uint32_t al = ah + 16384;
        const uint32_t bh = ah + 32768;
        const uint32_t bl = ah + 49152;
#pragma unroll
        for (int ks = 0; ks < 4; ks++) {
            const int k0 = ks * 16;
            uint32_t ahi[2][4], alo[2][4];
#pragma unroll
            for (int mt = 0; mt < 2; mt++) {
                uint32_t off = SWZ128((uint32_t)((a_row + mt * 16) * 128 + (k0 + a_kc8) * 2));
                LDSM_X4(ahi[mt][0], ahi[mt][1], ahi[mt][2], ahi[mt][3], ah + off);
                LDSM_X4(alo[mt][0], alo[mt][1], alo[mt][2], alo[mt][3], al + off);
            }
#pragma unroll
            for (int nt = 0; nt < 8; nt++) {
                uint32_t off = SWZ128((uint32_t)((b_row + nt * 8) * 128 + (k0 + b_kc8) * 2));
                uint32_t bhi[2], blo[2];
                LDSM_X2(bhi[0], bhi[1], bh + off);
                LDSM_X2(blo[0], blo[1], bl + off);
#pragma unroll
                for (int mt = 0; mt < 2; mt++) {
                    MMA16816(acc[mt][nt], ahi[mt], bhi);
                    MMA16816(acc[mt][nt], ahi[mt], blo);
                    MMA16816(acc[mt][nt], alo[mt], bhi);
                }
            }
        }
    };

    const int nk = g.K >> 6;
    ldg_tile(0);
    sts_tile(0);
    __syncthreads();
    for (int kt = 1; kt < nk; kt++) {
        ldg_tile(kt << 6);
        compute((kt - 1) & 1);
        sts_tile(kt & 1);
        __syncthreads();
    }
    compute((nk - 1) & 1);

    const int er = lane >> 2;
    const int ec = (lane & 3) * 2;
#pragma unroll
    for (int mt = 0; mt < 2; mt++) {
        const int m = bm + wm * 32 + mt * 16 + er;
#pragma unroll
        for (int nt = 0; nt < 8; nt++) {
            const int n = bn + wn * 64 + nt * 8 + ec;
            *(float2*)(g.C + (size_t)m * g.ldc + n) =
                make_float2(acc[mt][nt][0], acc[mt][nt][1]);
            *(float2*)(g.C + (size_t)(m + 8) * g.ldc + n) =
                make_float2(acc[mt][nt][2], acc[mt][nt][3]);
        }
    }
}

// =================== x_proj GEMM: BM=64, split-K(2), bf16 pre-split ===================
// z = br*2 + kh.  C partial = A[2048,1536][:, kh*768:+768] @ B[80, same]^T
struct G80B { const uint16_t* Ah[2]; const uint16_t* Al[2]; };

#define MMA80_BUF 36864
#define MMA80_SMEM (2 * MMA80_BUF)

__global__ void __launch_bounds__(256) gemm_mma80b(G80B g) {
    extern __shared__ char smem[];
    const uint32_t sb = smem_u32(smem);
    const int br = blockIdx.z >> 1;
    const int kh = blockIdx.z & 1;
    const uint16_t* __restrict__ Ah = g.Ah[br];
    const uint16_t* __restrict__ Al = g.Al[br];
    const uint16_t* __restrict__ Bh = g_xwh + (size_t)br * 80 * DI;
    const uint16_t* __restrict__ Bl = g_xwl + (size_t)br * 80 * DI;
    float* __restrict__ C = g_xdblp + (size_t)(br * 2 + kh) * BB * LL * 80;

    const int tid  = threadIdx.x;
    const int wid  = tid >> 5;
    const int lane = tid & 31;
    const int wm   = wid & 3;       // 16 rows each
    const int wn   = wid >> 2;      // 40 cols each
    const int bm = blockIdx.y * 64;
    const int kbase = kh * 768;

    uint4 rah[2], ral[2], rbh[3], rbl[3];
    float acc[5][4];
#pragma unroll
    for (int nt = 0; nt < 5; nt++)
#pragma unroll
        for (int q = 0; q < 4; q++) acc[nt][q] = 0.f;

    auto ldg_tile = [&](int k0) {
#pragma unroll
        for (int t = 0; t < 2; t++) {
            int i = tid + t * 256;
            int r = i >> 3, q = i & 7;
            size_t ao = (size_t)(bm + r) * DI + k0 + q * 8;
            rah[t] = *(const uint4*)(Ah + ao);
            ral[t] = *(const uint4*)(Al + ao);
        }
#pragma unroll
        for (int t = 0; t < 3; t++) {
            int i = tid + t * 256;
            if (i < 640) {
                int r = i >> 3, q = i & 7;
                size_t bo = (size_t)r * DI + k0 + q * 8;
                rbh[t] = *(const uint4*)(Bh + bo);
                rbl[t] = *(const uint4*)(Bl + bo);
            }
        }
    };
    auto sts_tile = [&](int buf) {
        const uint32_t base = sb + buf * MMA80_BUF;
#pragma unroll
        for (int t = 0; t < 2; t++) {
            int i = tid + t * 256;
            int r = i >> 3, q = i & 7;
            uint32_t off = SWZ128((uint32_t)(r * 128 + q * 16));
            STS128U(base + off, rah[t]);
            STS128U(base + 8192 + off, ral[t]);
        }
#pragma unroll
        for (int t = 0; t < 3; t++) {
            int i = tid + t * 256;
            if (i < 640) {
                int r = i >> 3, q = i & 7;
                uint32_t off = SWZ128((uint32_t)(r * 128 + q * 16));
                STS128U(base + 16384 + off, rbh[t]);
                STS128U(base + 26624 + off, rbl[t]);
            }
        }
    };

    const int a_row = wm * 16 + (lane & 7) + ((lane >> 3) & 1) * 8;
    const int a_kc8 = (lane >> 4) * 8;
    const int b_row = wn * 40 + (lane & 7);
    const int b_kc8 = ((lane >> 3) & 1) * 8;

    auto compute = [&](int buf) {
        const uint32_t ah = sb + buf * MMA80_BUF;
        const uint32_t al = ah + 8192;
        const uint32_t bh = ah + 16384;
        const uint32_t bl = ah + 26624;
#pragma unroll
        for (int ks = 0; ks < 4; ks++) {
            const int k0 = ks * 16;
            uint32_t ahi[4], alo[4];
            {
                uint32_t off = SWZ128((uint32_t)(a_row * 128 + (k0 + a_kc8) * 2));
                LDSM_X4(ahi[0], ahi[1], ahi[2], ahi[3], ah + off);
                LDSM_X4(alo[0], alo[1], alo[2], alo[3], al + off);
            }
#pragma unroll
            for (int nt = 0; nt < 5; nt++) {
                uint32_t off = SWZ128((uint32_t)((b_row + nt * 8) * 128 + (k0 + b_kc8) * 2));
                uint32_t bhi[2], blo[2];
                LDSM_X2(bhi[0], bhi[1], bh + off);
                LDSM_X2(blo[0], blo[1], bl + off);
                MMA16816(acc[nt], ahi, bhi);
                MMA16816(acc[nt], ahi, blo);
                MMA16816(acc[nt], alo, bhi);
            }
        }
    };

    const int nk = 768 >> 6;  // 12
    ldg_tile(kbase);
    sts_tile(0);
    __syncthreads();
    for (int kt = 1; kt < nk; kt++) {
        ldg_tile(kbase + (kt << 6));
        compute((kt - 1) & 1);
        sts_tile(kt & 1);
        __syncthreads();
    }
    compute((nk - 1) & 1);

    const int er = lane >> 2;
    const int ec = (lane & 3) * 2;
    const int m = bm + wm * 16 + er;
#pragma unroll
    for (int nt = 0; nt < 5; nt++) {
        const int n = wn * 40 + nt * 8 + ec;
        *(float2*)(C + (size_t)m * 80 + n) = make_float2(acc[nt][0], acc[nt][1]);
        *(float2*)(C + (size_t)(m + 8) * 80 + n) = make_float2(acc[nt][2], acc[nt][3]);
    }
}

// =================== xdbl combine: sum split-K partials -> f32 + bf16 split ===================
__global__ void __launch_bounds__(256) xdbl_combine() {
    const int n4 = (BB * LL * 80) / 4;   // 40960 per branch
    int idx = blockIdx.x * 256 + threadIdx.x;
    if (idx >= 2 * n4) return;
    int br = idx >= n4;
    size_t j = (size_t)(idx - br * n4) * 4;
    const float* p0 = g_xdblp + (size_t)(br * 2 + 0) * BB * LL * 80 + j;
    const float* p1 = g_xdblp + (size_t)(br * 2 + 1) * BB * LL * 80 + j;
    float4 a = *(const float4*)p0;
    float4 b = *(const float4*)p1;
    float4 s = make_float4(a.x + b.x, a.y + b.y, a.z + b.z, a.w + b.w);
    float* dst = br ? g_xdbl1 : g_xdbl0;
    *(float4*)(dst + j) = s;
    split_g(g_xdh + (size_t)br * BB * LL * 80, g_xdl + (size_t)br * BB * LL * 80, j, s);
}

// =================== dt GEMM: 128x128, K=48, bf16 pre-split, softplus ===================
struct G48B { float* C[2]; const float* bias[2]; };

__global__ void __launch_bounds__(256) gemm_mma48b(G48B g) {
    extern __shared__ char smem[];
    const uint32_t sb = smem_u32(smem);
    const int br = blockIdx.z;
    const uint16_t* __restrict__ Ahp = g_xdh + (size_t)br * BB * LL * 80;
    const uint16_t* __restrict__ Alp = g_xdl + (size_t)br * BB * LL * 80;
    const uint16_t* __restrict__ Bhp = g_dtwh + (size_t)br * DI * DTR;
    const uint16_t* __restrict__ Blp = g_dtwl + (size_t)br * DI * DTR;
    float* __restrict__ C = g.C[br];
    const float* __restrict__ bias = g.bias[br];

    const int tid  = threadIdx.x;
    const int wid  = tid >> 5;
    const int lane = tid & 31;
    const int wm   = wid & 3;
    const int wn   = wid >> 2;
    const int bm = blockIdx.y * 128;
    const int bn = blockIdx.x * 128;

    const uint32_t ah = sb, al = sb + 16384, bh = sb + 32768, bl = sb + 49152;
    const uint4 zz = make_uint4(0, 0, 0, 0);

#pragma unroll
    for (int t = 0; t < 4; t++) {
        int i = tid + t * 256;
        int r = i >> 3, q = i & 7;
        uint32_t off = SWZ128((uint32_t)(r * 128 + q * 16));
        uint4 vh = zz, vl = zz;
        if (q < 6) {
            size_t ao = (size_t)(bm + r) * 80 + q * 8;
            vh = *(const uint4*)(Ahp + ao);
            vl = *(const uint4*)(Alp + ao);
        }
        STS128U(ah + off, vh);
        STS128U(al + off, vl);
        uint4 wh = zz, wl = zz;
        if (q < 6) {
            size_t bo = (size_t)(bn + r) * DTR + q * 8;
            wh = *(const uint4*)(Bhp + bo);
            wl = *(const uint4*)(Blp + bo);
        }
        STS128U(bh + off, wh);
        STS128U(bl + off, wl);
    }
    __syncthreads();

    float acc[2][8][4];
#pragma unroll
    for (int mt = 0; mt < 2; mt++)
#pragma unroll
        for (int nt = 0; nt < 8; nt++)
#pragma unroll
            for (int q = 0; q < 4; q++) acc[mt][nt][q] = 0.f;

    const int a_row = wm * 32 + (lane & 7) + ((lane >> 3) & 1) * 8;
    const int a_kc8 = (lane >> 4) * 8;
    const int b_row = wn * 64 + (lane & 7);
    const int b_kc8 = ((lane >> 3) & 1) * 8;

#pragma unroll
    for (int ks = 0; ks < 3; ks++) {
        const int k0 = ks * 16;
        uint32_t ahi[2][4], alo[2][4];
#pragma unroll
        for (int mt = 0; mt < 2; mt++) {
            uint32_t off = SWZ128((uint32_t)((a_row + mt * 16) * 128 + (k0 + a_kc8) * 2));
            LDSM_X4(ahi[mt][0], ahi[mt][1], ahi[mt][2], ahi[mt][3], ah + off);
            LDSM_X4(alo[mt][0], alo[mt][1], alo[mt][2], alo[mt][3], al + off);
        }
#pragma unroll
        for (int nt = 0; nt < 8; nt++) {
            uint32_t off = SWZ128((uint32_t)((b_row + nt * 8) * 128 + (k0 + b_kc8) * 2));
            uint32_t bhi[2], blo[2];
            LDSM_X2(bhi[0], bhi[1], bh + off);
            LDSM_X2(blo[0], blo[1], bl + off);
#pragma unroll
            for (int mt = 0; mt < 2; mt++) {
                MMA16816(acc[mt][nt], ahi[mt], bhi);
                MMA16816(acc[mt][nt], ahi[mt], blo);
                MMA16816(acc[mt][nt], alo[mt], bhi);
            }
        }
    }

    const int er = lane >> 2;
    const int ec = (lane & 3) * 2;
#pragma unroll
    for (int mt = 0; mt < 2; mt++) {
        const int m = bm + wm * 32 + mt * 16 + er;
#pragma unroll
        for (int nt = 0; nt < 8; nt++) {
            const int n = bn + wn * 64 + nt * 8 + ec;
            const float b0 = bias[n], b1 = bias[n + 1];
            *(float2*)(C + (size_t)m * DI + n) = make_float2(
                softplus_f(acc[mt][nt][0] + b0), softplus_f(acc[mt][nt][1] + b1));
            *(float2*)(C + (size_t)(m + 8) * DI + n) = make_float2(
                softplus_f(acc[mt][nt][2] + b0), softplus_f(acc[mt][nt][3] + b1));
        }
    }
}

// ---------------- depthwise causal conv (K=4) + SiLU + bf16 split output ----------------
__global__ void __launch_bounds__(256)
conv_silu_k(const float* __restrict__ cw0, const float* __restrict__ cb0,
            const float* __restrict__ cw1, const float* __restrict__ cb1) {
    const size_t idx4 = (size_t)blockIdx.x * 256 + threadIdx.x;
    const int D4 = DI / 4;
    if (idx4 >= (size_t)BB * LL * D4) return;
    const int dq = (int)(idx4 % D4);
    const int l  = (int)((idx4 / D4) % LL);
    const int b  = (int)(idx4 / ((size_t)D4 * LL));
    const int d  = dq * 4;

    const float* xzb = g_xz + (size_t)b * LL * 2 * DI + d;

    float w0[4][4], w1[4][4];
#pragma unroll
    for (int j = 0; j < 4; j++) {
        float4 a = *(const float4*)(cw0 + (d + j) * 4);
        w0[j][0] = a.x; w0[j][1] = a.y; w0[j][2] = a.z; w0[j][3] = a.w;
        float4 c = *(const float4*)(cw1 + (d + j) * 4);
        w1[j][0] = c.x; w1[j][1] = c.y; w1[j][2] = c.z; w1[j][3] = c.w;
    }

    float s0[4], s1[4];
    {
        float4 b0 = *(const float4*)(cb0 + d);
        float4 b1 = *(const float4*)(cb1 + d);
        s0[0] = b0.x; s0[1] = b0.y; s0[2] = b0.z; s0[3] = b0.w;
        s1[0] = b1.x; s1[1] = b1.y; s1[2] = b1.z; s1[3] = b1.w;
    }

#pragma unroll
    for (int k = 0; k < 4; k++) {
        const int ls = l - 3 + k;
        if (ls >= 0) {
            float4 xv = *(const float4*)(xzb + (size_t)ls * 2 * DI);
            s0[0] += xv.x * w0[0][k]; s0[1] += xv.y * w0[1][k];
            s0[2] += xv.z * w0[2][k]; s0[3] += xv.w * w0[3][k];
            const int src = LL - 1 - l + 3 - k;
            float4 yv = *(const float4*)(xzb + (size_t)src * 2 * DI);
            s1[0] += yv.x * w1[0][k]; s1[1] += yv.y * w1[1][k];
            s1[2] += yv.z * w1[2][k]; s1[3] += yv.w * w1[3][k];
        }
    }

    float4 o0 = make_float4(silu_f(s0[0]), silu_f(s0[1]), silu_f(s0[2]), silu_f(s0[3]));
    float4 o1 = make_float4(silu_f(s1[0]), silu_f(s1[1]), silu_f(s1[2]), silu_f(s1[3]));
    const size_t o = ((size_t)b * LL + l) * DI + d;
    *(float4*)(g_xc0 + o) = o0;
    *(float4*)(g_xc1 + o) = o1;
    split_g(g_xc0h, g_xc0l, o, o0);
    split_g(g_xc1h, g_xc1l, o, o1);
}

// ---------------- ys combine: sum branches -> bf16 split ----------------
__global__ void __launch_bounds__(256) ys_split() {
    const size_t n4 = (size_t)BB * LL * DI / 4;
    size_t idx = (size_t)blockIdx.x * 256 + threadIdx.x;
    if (idx >= n4) return;
    size_t j = idx * 4;
    float4 a = *(const float4*)(g_ys0 + j);
    float4 b = *(const float4*)(g_ys1 + j);
    float4 s = make_float4(a.x + b.x, a.y + b.y, a.z + b.z, a.w + b.w);
    split_g(g_ysh, g_ysl, j, s);
}

// ---------------- selective scan pass A ----------------
__global__ void __launch_bounds__(128)
scan_passA(const float* __restrict__ AlogF, const float* __restrict__ AlogR) {
    const int tid = threadIdx.x;
    const int d = blockIdx.x * 128 + tid;
    const int seg = blockIdx.y;
    const int b = blockIdx.z & 1;
    const int br = blockIdx.z >> 1;

    const float* Alog   = br ? AlogR   : AlogF;
    const float* gdelta = br ? g_delta1 : g_delta0;
    const float* gxc    = br ? g_xc1    : g_xc0;
    const float* gxdbl  = br ? g_xdbl1  : g_xdbl0;
    float* gP = br ? g_segP1 : g_segP0;
    float* gH = br ? g_segH1 : g_segH0;

    float An[NST];
    bool fast = true;
#pragma unroll
    for (int n = 0; n < NST; n++) {
        An[n] = -__expf(Alog[d * NST + n]);
        if (fabsf(An[n] + (float)(n + 1)) > 1e-3f) fast = false;
    }

    float H[NST], P[NST];
#pragma unroll
    for (int n = 0; n < NST; n++) { H[n] = 0.f; P[n] = 1.f; }

    const size_t rowbase = (size_t)b * LL + (size_t)seg * SEGL;
    const float* dp = gdelta + rowbase * DI + d;
    const float* xp = gxc + rowbase * DI + d;
    const float* bc = gxdbl + rowbase * 80 + 48;

    __shared__ __align__(16) float sBC[32 * 32];

    for (int lc = 0; lc < SEGL; lc += 32) {
        __syncthreads();
        for (int i = tid; i < 32 * 32; i += 128) {
            int li = i >> 5, c = i & 31;
            sBC[i] = bc[(size_t)(lc + li) * 80 + c];
        }
        __syncthreads();
        for (int li = 0; li < 32; li++) {
            const int l = lc + li;
            const float delta = dp[(size_t)l * DI];
            const float x = xp[(size_t)l * DI];
            const float dx = delta * x;
            float bv[NST];
            const float4* q = (const float4*)&sBC[li * 32];
            ((float4*)bv)[0] = q[0]; ((float4*)bv)[1] = q[1];
            ((float4*)bv)[2] = q[2]; ((float4*)bv)[3] = q[3];
            if (fast) {
                const float e = __expf(-delta);
                float p = 1.f;
#pragma unroll
                for (int n = 0; n < NST; n++) {
                    p *= e;
                    H[n] = fmaf(p, H[n], dx * bv[n]);
                    P[n] *= p;
                }
            } else {
#pragma unroll
                for (int n = 0; n < NST; n++) {
                    float da = __expf(delta * An[n]);
                    H[n] = fmaf(da, H[n], dx * bv[n]);
                    P[n] *= da;
                }
            }
        }
    }

    const size_t o = (((size_t)b * NSEG + seg) * DI + d) * NST;
#pragma unroll
    for (int i = 0; i < 4; i++) {
        ((float4*)&gP[o])[i] = ((float4*)P)[i];
        ((float4*)&gH[o])[i] = ((float4*)H)[i];
    }
}

// ---------------- pass B: combine -> per-segment start states ----------------
__global__ void __launch_bounds__(128)
scan_passB() {
    const int idx = blockIdx.x * 128 + threadIdx.x;
    const int d = idx % DI;
    const int rest = idx / DI;
    const int b = rest & 1;
    const int br = rest >> 1;
    float* gP = br ? g_segP1 : g_segP0;
    const float* gH = br ? g_segH1 : g_segH0;

    float h[NST];
#pragma unroll
    for (int n = 0; n < NST; n++) h[n] = 0.f;

    for (int t = 0; t < NSEG; t++) {
        const size_t o = (((size_t)b * NSEG + t) * DI + d) * NST;
        float Pt[NST], Ht[NST];
        if (t < NSEG - 1) {
#pragma unroll
            for (int i = 0; i < 4; i++) {
                ((float4*)Pt)[i] = ((const float4*)&gP[o])[i];
                ((float4*)Ht)[i] = ((const float4*)&gH[o])[i];
            }
        }
#pragma unroll
        for (int i = 0; i < 4; i++) ((float4*)&gP[o])[i] = ((float4*)h)[i];
        if (t < NSEG - 1) {
#pragma unroll
            for (int n = 0; n < NST; n++) h[n] = fmaf(Pt[n], h[n], Ht[n]);
        }
    }
}

// ---------------- pass C: re-scan + gated output ----------------
__global__ void __launch_bounds__(128)
scan_passC(const float* __restrict__ AlogF, const float* __restrict__ AlogR,
           const float* __restrict__ Df, const float* __restrict__ Dr) {
    const int tid = threadIdx.x;
    const int d = blockIdx.x * 128 + tid;
    const int seg = blockIdx.y;
    const int b = blockIdx.z & 1;
    const int br = blockIdx.z >> 1;

    const float* Alog   = br ? AlogR   : AlogF;
    const float* gdelta = br ? g_delta1 : g_delta0;
    const float* gxc    = br ? g_xc1    : g_xc0;
    const float* gxdbl  = br ? g_xdbl1  : g_xdbl0;
    const float* gS = br ? g_segP1 : g_segP0;
    float* ys = br ? g_ys1 : g_ys0;

    float An[NST];
    bool fast = true;
#pragma unroll
    for (int n = 0; n < NST; n++) {
        An[n] = -__expf(Alog[d * NST + n]);
        if (fabsf(An[n] + (float)(n + 1)) > 1e-3f) fast = false;
    }

    float h[NST];
    {
        const size_t o = (((size_t)b * NSEG + seg) * DI + d) * NST;
#pragma unroll
        for (int i = 0; i < 4; i++) ((float4*)h)[i] = ((const float4*)&gS[o])[i];
    }

    const float Dd = (br ? Dr : Df)[d];
    const size_t rowbase = (size_t)b * LL + (size_t)seg * SEGL;
    const float* dp = gdelta + rowbase * DI + d;
    const float* xp = gxc + rowbase * DI + d;
    const float* bc = gxdbl + rowbase * 80 + 48;
    const float* gz = g_xz + (size_t)b * LL * 2 * DI + DI + d;

    __shared__ __align__(16) float sBC[32 * 32];

    for (int lc = 0; lc < SEGL; lc += 32) {
        __syncthreads();
        for (int i = tid; i < 32 * 32; i += 128) {
            int li = i >> 5, c = i & 31;
            sBC[i] = bc[(size_t)(lc + li) * 80 + c];
        }
        __syncthreads();
        for (int li = 0; li < 32; li++) {
            const int l = lc + li;
            const float delta = dp[(size_t)l * DI];
            const float x = xp[(size_t)l * DI];
            const float dx = delta * x;
            float bv[NST], cv[NST];
            const float4* q = (const float4*)&sBC[li * 32];
            ((float4*)bv)[0] = q[0]; ((float4*)bv)[1] = q[1];
            ((float4*)bv)[2] = q[2]; ((float4*)bv)[3] = q[3];
            ((float4*)cv)[0] = q[4]; ((float4*)cv)[1] = q[5];
            ((float4*)cv)[2] = q[6]; ((float4*)cv)[3] = q[7];
            float y = 0.f;
            if (fast) {
                const float e = __expf(-delta);
                float p = 1.f;
#pragma unroll
                for (int n = 0; n < NST; n++) {
                    p *= e;
                    h[n] = fmaf(p, h[n], dx * bv[n]);
                    y = fmaf(h[n], cv[n], y);
                }
            } else {
#pragma unroll
                for (int n = 0; n < NST; n++) {
                    float da = __expf(delta * An[n]);
                    h[n] = fmaf(da, h[n], dx * bv[n]);
                    y = fmaf(h[n], cv[n], y);
                }
            }
            const int gl = seg * SEGL + l;
            const int lo = br ? (LL - 1 - gl) : gl;
            const float zv = gz[(size_t)lo * 2 * DI];
            const float out = (y + x * Dd) * silu_f(zv);
            ys[((size_t)b * LL + lo) * DI + d] = out;
        }
    }
}

// ---------------- launch ----------------
extern "C" void kernel_launch(void* const* d_in, const int* in_sizes, int n_in,
                              void* d_out, int out_size) {
    const float* hidden     = (const float*)d_in[0];
    const float* in_proj_w  = (const float*)d_in[1];
    const float* conv_w     = (const float*)d_in[2];
    const float* conv_b     = (const float*)d_in[3];
    const float* x_proj_w   = (const float*)d_in[4];
    const float* dt_proj_w  = (const float*)d_in[5];
    const float* dt_proj_b  = (const float*)d_in[6];
    const float* A_log      = (const float*)d_in[7];
    const float* Dv         = (const float*)d_in[8];
    const float* conv_w_b   = (const float*)d_in[9];
    const float* conv_b_b   = (const float*)d_in[10];
    const float* x_proj_w_b = (const float*)d_in[11];
    const float* dt_proj_w_b= (const float*)d_in[12];
    const float* dt_proj_b_b= (const float*)d_in[13];
    const float* A_b_log    = (const float*)d_in[14];
    const float* D_b        = (const float*)d_in[15];
    const float* out_proj_w = (const float*)d_in[16];
    float* out = (float*)d_out;

    // symbol addresses
    float *p_xz, *p_delta0, *p_delta1;
    cudaGetSymbolAddress((void**)&p_xz, g_xz);
    cudaGetSymbolAddress((void**)&p_delta0, g_delta0);
    cudaGetSymbolAddress((void**)&p_delta1, g_delta1);
    uint16_t *p_hidh, *p_hidl, *p_w1h, *p_w1l, *p_xwh, *p_xwl, *p_dtwh, *p_dtwl;
    uint16_t *p_owh, *p_owl, *p_xc0h, *p_xc0l, *p_xc1h, *p_xc1l, *p_ysh, *p_ysl;
    cudaGetSymbolAddress((void**)&p_hidh, g_hidh);
    cudaGetSymbolAddress((void**)&p_hidl, g_hidl);
    cudaGetSymbolAddress((void**)&p_w1h, g_w1h);
    cudaGetSymbolAddress((void**)&p_w1l, g_w1l);
    cudaGetSymbolAddress((void**)&p_xwh, g_xwh);
    cudaGetSymbolAddress((void**)&p_xwl, g_xwl);
    cudaGetSymbolAddress((void**)&p_dtwh, g_dtwh);
    cudaGetSymbolAddress((void**)&p_dtwl, g_dtwl);
    cudaGetSymbolAddress((void**)&p_owh, g_owh);
    cudaGetSymbolAddress((void**)&p_owl, g_owl);
    cudaGetSymbolAddress((void**)&p_xc0h, g_xc0h);
    cudaGetSymbolAddress((void**)&p_xc0l, g_xc0l);
    cudaGetSymbolAddress((void**)&p_xc1h, g_xc1h);
    cudaGetSymbolAddress((void**)&p_xc1l, g_xc1l);
    cudaGetSymbolAddress((void**)&p_ysh, g_ysh);
    cudaGetSymbolAddress((void**)&p_ysl, g_ysl);

    cudaFuncSetAttribute(gemm_mma_b,  cudaFuncAttributeMaxDynamicSharedMemorySize, MMA_SMEM);
    cudaFuncSetAttribute(gemm_mma80b, cudaFuncAttributeMaxDynamicSharedMemorySize, MMA80_SMEM);
    cudaFuncSetAttribute(gemm_mma48b, cudaFuncAttributeMaxDynamicSharedMemorySize, 65536);

    const int M = BB * LL;  // 2048

    // 0) pre-split static tensors to bf16 hi/lo
    {
        SArgs sa{};
        int base = 0;
        auto add = [&](int k, const float* src, uint16_t* hi, uint16_t* lo, int n) {
            sa.s[k] = SSeg{src, hi, lo, base, n / 4};
            base += n / 4;
        };
        add(0, hidden,      p_hidh, p_hidl, M * DM);
        add(1, in_proj_w,   p_w1h,  p_w1l,  2 * DI * DM);
        add(2, x_proj_w,    p_xwh,            p_xwl,            80 * DI);
        add(3, x_proj_w_b,  p_xwh + 80 * DI,  p_xwl + 80 * DI,  80 * DI);
        add(4, dt_proj_w,   p_dtwh,           p_dtwl,           DI * DTR);
        add(5, dt_proj_w_b, p_dtwh + DI * DTR,p_dtwl + DI * DTR,DI * DTR);
        add(6, out_proj_w,  p_owh,  p_owl,  DM * DI);
        sa.total4 = base;
        split_many<<<(base + 255) / 256, 256>>>(sa);
    }

    // 1) xz = hidden @ in_proj_w^T
    {
        TBArgs a{};
        a.Ah = p_hidh; a.Al = p_hidl; a.Bh = p_w1h; a.Bl = p_w1l; a.C = p_xz;
        a.K = DM; a.lda = DM; a.ldb = DM; a.ldc = 2 * DI;
        gemm_mma_b<<<dim3(2 * DI / 128, M / 128), 256, MMA_SMEM>>>(a);
    }

    // 2) conv + silu (+ bf16 split of xc)
    conv_silu_k<<<(unsigned)(((size_t)M * (DI / 4) + 255) / 256), 256>>>(
        conv_w, conv_b, conv_w_b, conv_b_b);

    // 3) x_dbl partials (split-K), both branches
    {
        G80B a{};
        a.Ah[0] = p_xc0h; a.Ah[1] = p_xc1h;
        a.Al[0] = p_xc0l; a.Al[1] = p_xc1l;
        gemm_mma80b<<<dim3(1, M / 64, 4), 256, MMA80_SMEM>>>(a);
    }

    // 4) combine partials -> f32 xdbl + bf16 split
    xdbl_combine<<<(2 * (M * 80 / 4) + 255) / 256, 256>>>();

    // 5) delta = softplus(dt @ dt_proj_w^T + bias)
    {
        G48B a{};
        a.C[0] = p_delta0; a.C[1] = p_delta1;
        a.bias[0] = dt_proj_b; a.bias[1] = dt_proj_b_b;
        gemm_mma48b<<<dim3(DI / 128, M / 128, 2), 256, 65536>>>(a);
    }

    // 6) scan pass A
    scan_passA<<<dim3(DI / 128, NSEG - 1, 4), 128>>>(A_log, A_b_log);

    // 7) pass B
    scan_passB<<<(BB * 2 * DI) / 128, 128>>>();

    // 8) pass C
    scan_passC<<<dim3(DI / 128, NSEG, 4), 128>>>(A_log, A_b_log, Dv, D_b);

    // 9) ys sum + split
    ys_split<<<(unsigned)(((size_t)M * DI / 4 + 255) / 256), 256>>>();

    // 10) out = ysum @ out_proj_w^T
    {
        TBArgs a{};
        a.Ah = p_ysh; a.Al = p_ysl; a.Bh = p_owh; a.Bl = p_owl; a.C = out;
        a.K = DI; a.lda = DI; a.ldb = DI; a.ldc = DM;
        gemm_mma_b<<<dim3(DM / 128, M / 128), 256, MMA_SMEM>>>(a);
    }
}

// round 7
// speedup vs baseline: 4.0531x; 1.0010x over previous
#include <cuda_runtime.h>
#include <math.h>
#include <stdint.h>

#define DI   1536
#define DM   768
#define NST  16
#define DTR  48
#define BB   2
#define LL   1024
#define NSEG 32
#define SEGL (LL / NSEG)

// ---------------- scratch (device globals; no allocation allowed) ----------------
__device__ float g_xz[(size_t)BB * LL * 2 * DI];      // in_proj output (x | z)
__device__ float g_xc0[(size_t)BB * LL * DI];         // conv+silu fwd (f32, for scans)
__device__ float g_xc1[(size_t)BB * LL * DI];
__device__ float g_xdbl0[(size_t)BB * LL * 80];       // x_proj out (summed): [dt|B|C]
__device__ float g_xdbl1[(size_t)BB * LL * 80];
__device__ float g_delta0[(size_t)BB * LL * DI];
__device__ float g_delta1[(size_t)BB * LL * DI];
__device__ float g_segP0[(size_t)BB * NSEG * DI * NST];
__device__ float g_segP1[(size_t)BB * NSEG * DI * NST];
__device__ float g_segH0[(size_t)BB * NSEG * DI * NST];
__device__ float g_segH1[(size_t)BB * NSEG * DI * NST];
__device__ float g_ys0[(size_t)BB * LL * DI];
__device__ float g_ys1[(size_t)BB * LL * DI];
__device__ float g_xdblp[(size_t)8 * BB * LL * 80];   // x_proj partials [br*4+kq]

// bf16 hi/lo pre-split buffers
__device__ uint16_t g_hidh[(size_t)BB * LL * DM],     g_hidl[(size_t)BB * LL * DM];
__device__ uint16_t g_w1h[(size_t)2 * DI * DM],       g_w1l[(size_t)2 * DI * DM];
__device__ uint16_t g_xc0h[(size_t)BB * LL * DI],     g_xc0l[(size_t)BB * LL * DI];
__device__ uint16_t g_xc1h[(size_t)BB * LL * DI],     g_xc1l[(size_t)BB * LL * DI];
__device__ uint16_t g_xwh[(size_t)2 * 80 * DI],       g_xwl[(size_t)2 * 80 * DI];
__device__ uint16_t g_dtwh[(size_t)2 * DI * DTR],     g_dtwl[(size_t)2 * DI * DTR];
__device__ uint16_t g_owh[(size_t)DM * DI],           g_owl[(size_t)DM * DI];
__device__ uint16_t g_xdh[(size_t)2 * BB * LL * 80],  g_xdl[(size_t)2 * BB * LL * 80];
__device__ uint16_t g_ysh[(size_t)BB * LL * DI],      g_ysl[(size_t)BB * LL * DI];

// =================== helpers ===================
__device__ __forceinline__ uint32_t smem_u32(const void* p) {
    uint32_t a;
    asm("{ .reg .u64 t; cvta.to.shared.u64 t, %1; cvt.u32.u64 %0, t; }" : "=r"(a) : "l"(p));
    return a;
}
#define SWZ128(x) ((x) ^ (((x) >> 3) & 0x70))

__device__ __forceinline__ void split2(float a0, float a1, uint32_t& hi, uint32_t& lo) {
    asm("cvt.rn.bf16x2.f32 %0, %1, %2;" : "=r"(hi) : "f"(a1), "f"(a0));
    float h0 = __uint_as_float(hi << 16);
    float h1 = __uint_as_float(hi & 0xffff0000u);
    float r0 = a0 - h0, r1 = a1 - h1;
    asm("cvt.rn.bf16x2.f32 %0, %1, %2;" : "=r"(lo) : "f"(r1), "f"(r0));
}

__device__ __forceinline__ void split_g(uint16_t* hi, uint16_t* lo, size_t j, float4 v) {
    uint32_t h01, l01, h23, l23;
    split2(v.x, v.y, h01, l01);
    split2(v.z, v.w, h23, l23);
    *(uint2*)(hi + j) = make_uint2(h01, h23);
    *(uint2*)(lo + j) = make_uint2(l01, l23);
}

#define LDSM_X4(r0, r1, r2, r3, a) \
    asm volatile("ldmatrix.sync.aligned.m8n8.x4.shared.b16 {%0,%1,%2,%3}, [%4];" \
                 : "=r"(r0), "=r"(r1), "=r"(r2), "=r"(r3) : "r"(a))
#define LDSM_X2(r0, r1, a) \
    asm volatile("ldmatrix.sync.aligned.m8n8.x2.shared.b16 {%0,%1}, [%2];" \
                 : "=r"(r0), "=r"(r1) : "r"(a))
#define MMA16816(c, a, b) \
    asm volatile("mma.sync.aligned.m16n8k16.row.col.f32.bf16.bf16.f32 " \
                 "{%0,%1,%2,%3}, {%4,%5,%6,%7}, {%8,%9}, {%0,%1,%2,%3};" \
                 : "+f"((c)[0]), "+f"((c)[1]), "+f"((c)[2]), "+f"((c)[3]) \
                 : "r"((a)[0]), "r"((a)[1]), "r"((a)[2]), "r"((a)[3]), \
                   "r"((b)[0]), "r"((b)[1]))
#define STS128U(addr, v) \
    asm volatile("st.shared.v4.b32 [%0], {%1,%2,%3,%4};" \
                 :: "r"(addr), "r"((v).x), "r"((v).y), "r"((v).z), "r"((v).w) : "memory")

__device__ __forceinline__ float silu_f(float v) {
    return v / (1.f + __expf(-v));
}
__device__ __forceinline__ float softplus_f(float v) {
    return fmaxf(v, 0.f) + __logf(1.f + __expf(-fabsf(v)));
}

// =================== split_many: pre-split static tensors ===================
struct SSeg { const float* src; uint16_t* hi; uint16_t* lo; int base4; int n4; };
struct SArgs { SSeg s[7]; int total4; };

__global__ void __launch_bounds__(256) split_many(SArgs a) {
    int idx = blockIdx.x * 256 + threadIdx.x;
    if (idx >= a.total4) return;
#pragma unroll
    for (int k = 0; k < 7; k++) {
        int j = idx - a.s[k].base4;
        if (j >= 0 && j < a.s[k].n4) {
            float4 v = *(const float4*)(a.s[k].src + (size_t)j * 4);
            split_g(a.s[k].hi, a.s[k].lo, (size_t)j * 4, v);
            return;
        }
    }
}

// =================== NT GEMM 128xBN (bf16 pre-split, single-buffer pipeline) ===================
struct TBArgs {
    const uint16_t* Ah; const uint16_t* Al;
    const uint16_t* Bh; const uint16_t* Bl;
    float* C; int K, lda, ldb, ldc;
};

// smem: Ah 16K | Al 16K | Bh BN*128 | Bl BN*128
template <int BN>
__global__ void __launch_bounds__(256) gemm_mma_s(TBArgs g) {
    extern __shared__ char smem[];
    const uint32_t sb = smem_u32(smem);
    constexpr int NT = BN / 16;               // 8-col blocks per warp col
    constexpr int BHOFF = 32768;
    constexpr int BLOFF = 32768 + BN * 128;
    constexpr int BITER = (BN * 8) / 256;

    const int tid  = threadIdx.x;
    const int wid  = tid >> 5;
    const int lane = tid & 31;
    const int wm   = wid & 3;
    const int wn   = wid >> 2;
    const int bm = blockIdx.y * 128;
    const int bn = blockIdx.x * BN;

    uint4 rah[4], ral[4], rbh[BITER], rbl[BITER];
    float acc[2][NT][4];
#pragma unroll
    for (int mt = 0; mt < 2; mt++)
#pragma unroll
        for (int nt = 0; nt < NT; nt++)
#pragma unroll
            for (int q = 0; q < 4; q++) acc[mt][nt][q] = 0.f;

    auto ldg_tile = [&](int k0) {
#pragma unroll
        for (int t = 0; t < 4; t++) {
            int i = tid + t * 256;
            int r = i >> 3, q = i & 7;
            size_t ao = (size_t)(bm + r) * g.lda + k0 + q * 8;
            rah[t] = *(const uint4*)(g.Ah + ao);
            ral[t] = *(const uint4*)(g.Al + ao);
        }
#pragma unroll
        for (int t = 0; t < BITER; t++) {
            int i = tid + t * 256;
            int r = i >> 3, q = i & 7;
            size_t bo = (size_t)(bn + r) * g.ldb + k0 + q * 8;
            rbh[t] = *(const uint4*)(g.Bh + bo);
            rbl[t] = *(const uint4*)(g.Bl + bo);
        }
    };
    auto sts_tile = [&]() {
#pragma unroll
        for (int t = 0; t < 4; t++) {
            int i = tid + t * 256;
            int r = i >> 3, q = i & 7;
            uint32_t off = SWZ128((uint32_t)(r * 128 + q * 16));
            STS128U(sb + off, rah[t]);
            STS128U(sb + 16384 + off, ral[t]);
        }
#pragma unroll
        for (int t = 0; t < BITER; t++) {
            int i = tid + t * 256;
            int r = i >> 3, q = i & 7;
            uint32_t off = SWZ128((uint32_t)(r * 128 + q * 16));
            STS128U(sb + BHOFF + off, rbh[t]);
            STS128U(sb + BLOFF + off, rbl[t]);
        }
    };

    const int a_row = wm * 32 + (lane & 7) + ((lane >> 3) & 1) * 8;
    const int a_kc8 = (lane >> 4) * 8;
    const int b_row = wn * (BN / 2) + (lane & 7);
    const int b_kc8 = ((lane >> 3) & 1) * 8;

    auto compute = [&]() {
#pragma unroll
        for (int ks = 0; ks < 4; ks++) {
            const int k0 = ks * 16;
            uint32_t ahi[2][4], alo[2][4];
#pragma unroll
            for (int mt = 0; mt < 2; mt++) {
                uint32_t off = SWZ128((uint32_t)((a_row + mt * 16) * 128 + (k0 + a_kc8) * 2));
                LDSM_X4(ahi[mt][0], ahi[mt][1], ahi[mt][2], ahi[mt][3], sb + off);
                LDSM_X4(alo[mt][0], alo[mt][1], alo[mt][2], alo[mt][3], sb + 16384 + off);
            }
#pragma unroll
            for (int nt = 0; nt < NT; nt++) {
                uint32_t off = SWZ128((uint32_t)((b_row + nt * 8) * 128 + (k0 + b_kc8) * 2));
                uint32_t bhi[2], blo[2];
                LDSM_X2(bhi[0], bhi[1], sb + BHOFF + off);
                LDSM_X2(blo[0], blo[1], sb + BLOFF + off);
#pragma unroll
                for (int mt = 0; mt < 2; mt++) {
                    MMA16816(acc[mt][nt], ahi[mt], bhi);
                    MMA16816(acc[mt][nt], ahi[mt], blo);
                    MMA16816(acc[mt][nt], alo[mt], bhi);
                }
            }
        }
    };

    const int nk = g.K >> 6;
    ldg_tile(0);
    sts_tile();
    __syncthreads();
    for (int kt = 1; kt < nk; kt++) {
        ldg_tile(kt << 6);        // LDG latency overlapped with compute below
        compute();
        __syncthreads();          // everyone done reading smem
        sts_tile();
        __syncthreads();          // new tile visible
    }
    compute();

    const int er = lane >> 2;
    const int ec = (lane & 3) * 2;
#pragma unroll
    for (int mt = 0; mt < 2; mt++) {
        const int m = bm + wm * 32 + mt * 16 + er;
#pragma unroll
        for (int nt = 0; nt < NT; nt++) {
            const int n = bn + wn * (BN / 2) + nt * 8 + ec;
            *(float2*)(g.C + (size_t)m * g.ldc + n) =
                make_float2(acc[mt][nt][0], acc[mt][nt][1]);
            *(float2*)(g.C + (size_t)(m + 8) * g.ldc + n) =
                make_float2(acc[mt][nt][2], acc[mt][nt][3]);
        }
    }
}

// =================== x_proj GEMM: BM=64, split-K(4), single buffer ===================
// z = br*4 + kq.  partial = A[:, kq*384:+384] @ B[80, same]^T
struct G80B { const uint16_t* Ah[2]; const uint16_t* Al[2]; };

#define MMA80_SMEM 36864   // Ah 8K | Al 8K | Bh 10K | Bl 10K (+pad)

__global__ void __launch_bounds__(256) gemm_mma80b(G80B g) {
    extern __shared__ char smem[];
    const uint32_t sb = smem_u32(smem);
    const int br = blockIdx.z >> 2;
    const int kq = blockIdx.z & 3;
    const uint16_t* __restrict__ Ah = g.Ah[br];
    const uint16_t* __restrict__ Al = g.Al[br];
    const uint16_t* __restrict__ Bh = g_xwh + (size_t)br * 80 * DI;
    const uint16_t* __restrict__ Bl = g_xwl + (size_t)br * 80 * DI;
    float* __restrict__ C = g_xdblp + (size_t)(br * 4 + kq) * BB * LL * 80;

    const int tid  = threadIdx.x;
    const int wid  = tid >> 5;
    const int lane = tid & 31;
    const int wm   = wid & 3;       // 16 rows each
    const int wn   = wid >> 2;      // 40 cols each
    const int bm = blockIdx.y * 64;
    const int kbase = kq * 384;

    uint4 rah[2], ral[2], rbh[3], rbl[3];
    float acc[5][4];
#pragma unroll
    for (int nt = 0; nt < 5; nt++)
#pragma unroll
        for (int q = 0; q < 4; q++) acc[nt][q] = 0.f;

    auto ldg_tile = [&](int k0) {
#pragma unroll
        for (int t = 0; t < 2; t++) {
            int i = tid + t * 256;
            int r = i >> 3, q = i & 7;
            size_t ao = (size_t)(bm + r) * DI + k0 + q * 8;
            rah[t] = *(const uint4*)(Ah + ao);
            ral[t] = *(const uint4*)(Al + ao);
        }
#pragma unroll
        for (int t = 0; t < 3; t++) {
            int i = tid + t * 256;
            if (i < 640) {
                int r = i >> 3, q = i & 7;
                size_t bo = (size_t)r * DI + k0 + q * 8;
                rbh[t] = *(const uint4*)(Bh + bo);
                rbl[t] = *(const uint4*)(Bl + bo);
            }
        }
    };
    auto sts_tile = [&]() {
#pragma unroll
        for (int t = 0; t < 2; t++) {
            int i = tid + t * 256;
            int r = i >> 3, q = i & 7;
            uint32_t off = SWZ128((uint32_t)(r * 128 + q * 16));
            STS128U(sb + off, rah[t]);
            STS128U(sb + 8192 + off, ral[t]);
        }
#pragma unroll
        for (int t = 0; t < 3; t++) {
            int i = tid + t * 256;
            if (i < 640) {
                int r = i >> 3, q = i & 7;
                uint32_t off = SWZ128((uint32_t)(r * 128 + q * 16));
                STS128U(sb + 16384 + off, rbh[t]);
                STS128U(sb + 26624 + off, rbl[t]);
            }
        }
    };

    const int a_row = wm * 16 + (lane & 7) + ((lane >> 3) & 1) * 8;
    const int a_kc8 = (lane >> 4) * 8;
    const int b_row = wn * 40 + (lane & 7);
    const int b_kc8 = ((lane >> 3) & 1) * 8;

    auto compute = [&]() {
#pragma unroll
        for (int ks = 0; ks < 4; ks++) {
            const int k0 = ks * 16;
            uint32_t ahi[4], alo[4];
            {
                uint32_t off = SWZ128((uint32_t)(a_row * 128 + (k0 + a_kc8) * 2));
                LDSM_X4(ahi[0], ahi[1], ahi[2], ahi[3], sb + off);
                LDSM_X4(alo[0], alo[1], alo[2], alo[3], sb + 8192 + off);
            }
#pragma unroll
            for (int nt = 0; nt < 5; nt++) {
                uint32_t off = SWZ128((uint32_t)((b_row + nt * 8) * 128 + (k0 + b_kc8) * 2));
                uint32_t bhi[2], blo[2];
                LDSM_X2(bhi[0], bhi[1], sb + 16384 + off);
                LDSM_X2(blo[0], blo[1], sb + 26624 + off);
                MMA16816(acc[nt], ahi, bhi);
                MMA16816(acc[nt], ahi, blo);
                MMA16816(acc[nt], alo, bhi);
            }
        }
    };

    const int nk = 384 >> 6;  // 6
    ldg_tile(kbase);
    sts_tile();
    __syncthreads();
    for (int kt = 1; kt < nk; kt++) {
        ldg_tile(kbase + (kt << 6));
        compute();
        __syncthreads();
        sts_tile();
        __syncthreads();
    }
    compute();

    const int er = lane >> 2;
    const int ec = (lane & 3) * 2;
    const int m = bm + wm * 16 + er;
#pragma unroll
    for (int nt = 0; nt < 5; nt++) {
        const int n = wn * 40 + nt * 8 + ec;
        *(float2*)(C + (size_t)m * 80 + n) = make_float2(acc[nt][0], acc[nt][1]);
        *(float2*)(C + (size_t)(m + 8) * 80 + n) = make_float2(acc[nt][2], acc[nt][3]);
    }
}

// =================== xdbl combine: sum 4 split-K partials -> f32 + bf16 split ===================
__global__ void __launch_bounds__(256) xdbl_combine() {
    const int n4 = (BB * LL * 80) / 4;
    int idx = blockIdx.x * 256 + threadIdx.x;
    if (idx >= 2 * n4) return;
    int br = idx >= n4;
    size_t j = (size_t)(idx - br * n4) * 4;
    float4 s = make_float4(0.f, 0.f, 0.f, 0.f);
#pragma unroll
    for (int k = 0; k < 4; k++) {
        float4 a = *(const float4*)(g_xdblp + (size_t)(br * 4 + k) * BB * LL * 80 + j);
        s.x += a.x; s.y += a.y; s.z += a.z; s.w += a.w;
    }
    float* dst = br ? g_xdbl1 : g_xdbl0;
    *(float4*)(dst + j) = s;
    split_g(g_xdh + (size_t)br * BB * LL * 80, g_xdl + (size_t)br * BB * LL * 80, j, s);
}

// =================== dt GEMM: 128x128, K=48, bf16 pre-split, softplus ===================
struct G48B { float* C[2]; const float* bias[2]; };

__global__ void __launch_bounds__(256) gemm_mma48b(G48B g) {
    extern __shared__ char smem[];
    const uint32_t sb = smem_u32(smem);
    const int br = blockIdx.z;
    const uint16_t* __restrict__ Ahp = g_xdh + (size_t)br * BB * LL * 80;
    const uint16_t* __restrict__ Alp = g_xdl + (size_t)br * BB * LL * 80;
    const uint16_t* __restrict__ Bhp = g_dtwh + (size_t)br * DI * DTR;
    const uint16_t* __restrict__ Blp = g_dtwl + (size_t)br * DI * DTR;
    float* __restrict__ C = g.C[br];
    const float* __restrict__ bias = g.bias[br];

    const int tid  = threadIdx.x;
    const int wid  = tid >> 5;
    const int lane = tid & 31;
    const int wm   = wid & 3;
    const int wn   = wid >> 2;
    const int bm = blockIdx.y * 128;
    const int bn = blockIdx.x * 128;

    const uint32_t ah = sb, al = sb + 16384, bh = sb + 32768, bl = sb + 49152;
    const uint4 zz = make_uint4(0, 0, 0, 0);

#pragma unroll
    for (int t = 0; t < 4; t++) {
        int i = tid + t * 256;
        int r = i >> 3, q = i & 7;
        uint32_t off = SWZ128((uint32_t)(r * 128 + q * 16));
        uint4 vh = zz, vl = zz;
        if (q < 6) {
            size_t ao = (size_t)(bm + r) * 80 + q * 8;
            vh = *(const uint4*)(Ahp + ao);
            vl = *(const uint4*)(Alp + ao);
        }
        STS128U(ah + off, vh);
        STS128U(al + off, vl);
        uint4 wh = zz, wl = zz;
        if (q < 6) {
            size_t bo = (size_t)(bn + r) * DTR + q * 8;
            wh = *(const uint4*)(Bhp + bo);
            wl = *(const uint4*)(Blp + bo);
        }
        STS128U(bh + off, wh);
        STS128U(bl + off, wl);
    }
    __syncthreads();

    float acc[2][8][4];
#pragma unroll
    for (int mt = 0; mt < 2; mt++)
#pragma unroll
        for (int nt = 0; nt < 8; nt++)
#pragma unroll
            for (int q = 0; q < 4; q++) acc[mt][nt][q] = 0.f;

    const int a_row = wm * 32 + (lane & 7) + ((lane >> 3) & 1) * 8;
    const int a_kc8 = (lane >> 4) * 8;
    const int b_row = wn * 64 + (lane & 7);
    const int b_kc8 = ((lane >> 3) & 1) * 8;

#pragma unroll
    for (int ks = 0; ks < 3; ks++) {
        const int k0 = ks * 16;
        uint32_t ahi[2][4], alo[2][4];
#pragma unroll
        for (int mt = 0; mt < 2; mt++) {
            uint32_t off = SWZ128((uint32_t)((a_row + mt * 16) * 128 + (k0 + a_kc8) * 2));
            LDSM_X4(ahi[mt][0], ahi[mt][1], ahi[mt][2], ahi[mt][3], ah + off);
            LDSM_X4(alo[mt][0], alo[mt][1], alo[mt][2], alo[mt][3], al + off);
        }
#pragma unroll
        for (int nt = 0; nt < 8; nt++) {
            uint32_t off = SWZ128((uint32_t)((b_row + nt * 8) * 128 + (k0 + b_kc8) * 2));
            uint32_t bhi[2], blo[2];
            LDSM_X2(bhi[0], bhi[1], bh + off);
            LDSM_X2(blo[0], blo[1], bl + off);
#pragma unroll
            for (int mt = 0; mt < 2; mt++) {
                MMA16816(acc[mt][nt], ahi[mt], bhi);
                MMA16816(acc[mt][nt], ahi[mt], blo);
                MMA16816(acc[mt][nt], alo[mt], bhi);
            }
        }
    }

    const int er = lane >> 2;
    const int ec = (lane & 3) * 2;
#pragma unroll
    for (int mt = 0; mt < 2; mt++) {
        const int m = bm + wm * 32 + mt * 16 + er;
#pragma unroll
        for (int nt = 0; nt < 8; nt++) {
            const int n = bn + wn * 64 + nt * 8 + ec;
            const float b0 = bias[n], b1 = bias[n + 1];
            *(float2*)(C + (size_t)m * DI + n) = make_float2(
                softplus_f(acc[mt][nt][0] + b0), softplus_f(acc[mt][nt][1] + b1));
            *(float2*)(C + (size_t)(m + 8) * DI + n) = make_float2(
                softplus_f(acc[mt][nt][2] + b0), softplus_f(acc[mt][nt][3] + b1));
        }
    }
}

// ---------------- depthwise causal conv (K=4) + SiLU + bf16 split output ----------------
__global__ void __launch_bounds__(256)
conv_silu_k(const float* __restrict__ cw0, const float* __restrict__ cb0,
            const float* __restrict__ cw1, const float* __restrict__ cb1) {
    const size_t idx4 = (size_t)blockIdx.x * 256 + threadIdx.x;
    const int D4 = DI / 4;
    if (idx4 >= (size_t)BB * LL * D4) return;
    const int dq = (int)(idx4 % D4);
    const int l  = (int)((idx4 / D4) % LL);
    const int b  = (int)(idx4 / ((size_t)D4 * LL));
    const int d  = dq * 4;

    const float* xzb = g_xz + (size_t)b * LL * 2 * DI + d;

    float w0[4][4], w1[4][4];
#pragma unroll
    for (int j = 0; j < 4; j++) {
        float4 a = *(const float4*)(cw0 + (d + j) * 4);
        w0[j][0] = a.x; w0[j][1] = a.y; w0[j][2] = a.z; w0[j][3] = a.w;
        float4 c = *(const float4*)(cw1 + (d + j) * 4);
        w1[j][0] = c.x; w1[j][1] = c.y; w1[j][2] = c.z; w1[j][3] = c.w;
    }

    float s0[4], s1[4];
    {
        float4 b0 = *(const float4*)(cb0 + d);
        float4 b1 = *(const float4*)(cb1 + d);
        s0[0] = b0.x; s0[1] = b0.y; s0[2] = b0.z; s0[3] = b0.w;
        s1[0] = b1.x; s1[1] = b1.y; s1[2] = b1.z; s1[3] = b1.w;
    }

#pragma unroll
    for (int k = 0; k < 4; k++) {
        const int ls = l - 3 + k;
        if (ls >= 0) {
            float4 xv = *(const float4*)(xzb + (size_t)ls * 2 * DI);
            s0[0] += xv.x * w0[0][k]; s0[1] += xv.y * w0[1][k];
            s0[2] += xv.z * w0[2][k]; s0[3] += xv.w * w0[3][k];
            const int src = LL - 1 - l + 3 - k;
            float4 yv = *(const float4*)(xzb + (size_t)src * 2 * DI);
            s1[0] += yv.x * w1[0][k]; s1[1] += yv.y * w1[1][k];
            s1[2] += yv.z * w1[2][k]; s1[3] += yv.w * w1[3][k];
        }
    }

    float4 o0 = make_float4(silu_f(s0[0]), silu_f(s0[1]), silu_f(s0[2]), silu_f(s0[3]));
    float4 o1 = make_float4(silu_f(s1[0]), silu_f(s1[1]), silu_f(s1[2]), silu_f(s1[3]));
    const size_t o = ((size_t)b * LL + l) * DI + d;
    *(float4*)(g_xc0 + o) = o0;
    *(float4*)(g_xc1 + o) = o1;
    split_g(g_xc0h, g_xc0l, o, o0);
    split_g(g_xc1h, g_xc1l, o, o1);
}

// ---------------- ys combine: sum branches -> bf16 split ----------------
__global__ void __launch_bounds__(256) ys_split() {
    const size_t n4 = (size_t)BB * LL * DI / 4;
    size_t idx = (size_t)blockIdx.x * 256 + threadIdx.x;
    if (idx >= n4) return;
    size_t j = idx * 4;
    float4 a = *(const float4*)(g_ys0 + j);
    float4 b = *(const float4*)(g_ys1 + j);
    float4 s = make_float4(a.x + b.x, a.y + b.y, a.z + b.z, a.w + b.w);
    split_g(g_ysh, g_ysl, j, s);
}

// ---------------- selective scan pass A ----------------
__global__ void __launch_bounds__(128)
scan_passA(const float* __restrict__ AlogF, const float* __restrict__ AlogR) {
    const int tid = threadIdx.x;
    const int d = blockIdx.x * 128 + tid;
    const int seg = blockIdx.y;
    const int b = blockIdx.z & 1;
    const int br = blockIdx.z >> 1;

    const float* Alog   = br ? AlogR   : AlogF;
    const float* gdelta = br ? g_delta1 : g_delta0;
    const float* gxc    = br ? g_xc1    : g_xc0;
    const float* gxdbl  = br ? g_xdbl1  : g_xdbl0;
    float* gP = br ? g_segP1 : g_segP0;
    float* gH = br ? g_segH1 : g_segH0;

    float An[NST];
    bool fast = true;
#pragma unroll
    for (int n = 0; n < NST; n++) {
        An[n] = -__expf(Alog[d * NST + n]);
        if (fabsf(An[n] + (float)(n + 1)) > 1e-3f) fast = false;
    }

    float H[NST], P[NST];
#pragma unroll
    for (int n = 0; n < NST; n++) { H[n] = 0.f; P[n] = 1.f; }

    const size_t rowbase = (size_t)b * LL + (size_t)seg * SEGL;
    const float* dp = gdelta + rowbase * DI + d;
    const float* xp = gxc + rowbase * DI + d;
    const float* bc = gxdbl + rowbase * 80 + 48;

    __shared__ __align__(16) float sBC[32 * 32];

    for (int lc = 0; lc < SEGL; lc += 32) {
        __syncthreads();
        for (int i = tid; i < 32 * 32; i += 128) {
            int li = i >> 5, c = i & 31;
            sBC[i] = bc[(size_t)(lc + li) * 80 + c];
        }
        __syncthreads();
        for (int li = 0; li < 32; li++) {
            const int l = lc + li;
            const float delta = dp[(size_t)l * DI];
            const float x = xp[(size_t)l * DI];
            const float dx = delta * x;
            float bv[NST];
            const float4* q = (const float4*)&sBC[li * 32];
            ((float4*)bv)[0] = q[0]; ((float4*)bv)[1] = q[1];
            ((float4*)bv)[2] = q[2]; ((float4*)bv)[3] = q[3];
            if (fast) {
                const float e = __expf(-delta);
                float p = 1.f;
#pragma unroll
                for (int n = 0; n < NST; n++) {
                    p *= e;
                    H[n] = fmaf(p, H[n], dx * bv[n]);
                    P[n] *= p;
                }
            } else {
#pragma unroll
                for (int n = 0; n < NST; n++) {
                    float da = __expf(delta * An[n]);
                    H[n] = fmaf(da, H[n], dx * bv[n]);
                    P[n] *= da;
                }
            }
        }
    }

    const size_t o = (((size_t)b * NSEG + seg) * DI + d) * NST;
#pragma unroll
    for (int i = 0; i < 4; i++) {
        ((float4*)&gP[o])[i] = ((float4*)P)[i];
        ((float4*)&gH[o])[i] = ((float4*)H)[i];
    }
}

// ---------------- pass B: combine -> per-segment start states ----------------
__global__ void __launch_bounds__(128)
scan_passB() {
    const int idx = blockIdx.x * 128 + threadIdx.x;
    const int d = idx % DI;
    const int rest = idx / DI;
    const int b = rest & 1;
    const int br = rest >> 1;
    float* gP = br ? g_segP1 : g_segP0;
    const float* gH = br ? g_segH1 : g_segH0;

    float h[NST];
#pragma unroll
    for (int n = 0; n < NST; n++) h[n] = 0.f;

    for (int t = 0; t < NSEG; t++) {
        const size_t o = (((size_t)b * NSEG + t) * DI + d) * NST;
        float Pt[NST], Ht[NST];
        if (t < NSEG - 1) {
#pragma unroll
            for (int i = 0; i < 4; i++) {
                ((float4*)Pt)[i] = ((const float4*)&gP[o])[i];
                ((float4*)Ht)[i] = ((const float4*)&gH[o])[i];
            }
        }
#pragma unroll
        for (int i = 0; i < 4; i++) ((float4*)&gP[o])[i] = ((float4*)h)[i];
        if (t < NSEG - 1) {
#pragma unroll
            for (int n = 0; n < NST; n++) h[n] = fmaf(Pt[n], h[n], Ht[n]);
        }
    }
}

// ---------------- pass C: re-scan + gated output ----------------
__global__ void __launch_bounds__(128)
scan_passC(const float* __restrict__ AlogF, const float* __restrict__ AlogR,
           const float* __restrict__ Df, const float* __restrict__ Dr) {
    const int tid = threadIdx.x;
    const int d = blockIdx.x * 128 + tid;
    const int seg = blockIdx.y;
    const int b = blockIdx.z & 1;
    const int br = blockIdx.z >> 1;

    const float* Alog   = br ? AlogR   : AlogF;
    const float* gdelta = br ? g_delta1 : g_delta0;
    const float* gxc    = br ? g_xc1    : g_xc0;
    const float* gxdbl  = br ? g_xdbl1  : g_xdbl0;
    const float* gS = br ? g_segP1 : g_segP0;
    float* ys = br ? g_ys1 : g_ys0;

    float An[NST];
    bool fast = true;
#pragma unroll
    for (int n = 0; n < NST; n++) {
        An[n] = -__expf(Alog[d * NST + n]);
        if (fabsf(An[n] + (float)(n + 1)) > 1e-3f) fast = false;
    }

    float h[NST];
    {
        const size_t o = (((size_t)b * NSEG + seg) * DI + d) * NST;
#pragma unroll
        for (int i = 0; i < 4; i++) ((float4*)h)[i] = ((const float4*)&gS[o])[i];
    }

    const float Dd = (br ? Dr : Df)[d];
    const size_t rowbase = (size_t)b * LL + (size_t)seg * SEGL;
    const float* dp = gdelta + rowbase * DI + d;
    const float* xp = gxc + rowbase * DI + d;
    const float* bc = gxdbl + rowbase * 80 + 48;
    const float* gz = g_xz + (size_t)b * LL * 2 * DI + DI + d;

    __shared__ __align__(16) float sBC[32 * 32];

    for (int lc = 0; lc < SEGL; lc += 32) {
        __syncthreads();
        for (int i = tid; i < 32 * 32; i += 128) {
            int li = i >> 5, c = i & 31;
            sBC[i] = bc[(size_t)(lc + li) * 80 + c];
        }
        __syncthreads();
        for (int li = 0; li < 32; li++) {
            const int l = lc + li;
            const float delta = dp[(size_t)l * DI];
            const float x = xp[(size_t)l * DI];
            const float dx = delta * x;
            float bv[NST], cv[NST];
            const float4* q = (const float4*)&sBC[li * 32];
            ((float4*)bv)[0] = q[0]; ((float4*)bv)[1] = q[1];
            ((float4*)bv)[2] = q[2]; ((float4*)bv)[3] = q[3];
            ((float4*)cv)[0] = q[4]; ((float4*)cv)[1] = q[5];
            ((float4*)cv)[2] = q[6]; ((float4*)cv)[3] = q[7];
            float y = 0.f;
            if (fast) {
                const float e = __expf(-delta);
                float p = 1.f;
#pragma unroll
                for (int n = 0; n < NST; n++) {
                    p *= e;
                    h[n] = fmaf(p, h[n], dx * bv[n]);
                    y = fmaf(h[n], cv[n], y);
                }
            } else {
#pragma unroll
                for (int n = 0; n < NST; n++) {
                    float da = __expf(delta * An[n]);
                    h[n] = fmaf(da, h[n], dx * bv[n]);
                    y = fmaf(h[n], cv[n], y);
                }
            }
            const int gl = seg * SEGL + l;
            const int lo = br ? (LL - 1 - gl) : gl;
            const float zv = gz[(size_t)lo * 2 * DI];
            const float out = (y + x * Dd) * silu_f(zv);
            ys[((size_t)b * LL + lo) * DI + d] = out;
        }
    }
}

// ---------------- launch ----------------
extern "C" void kernel_launch(void* const* d_in, const int* in_sizes, int n_in,
                              void* d_out, int out_size) {
    const float* hidden     = (const float*)d_in[0];
    const float* in_proj_w  = (const float*)d_in[1];
    const float* conv_w     = (const float*)d_in[2];
    const float* conv_b     = (const float*)d_in[3];
    const float* x_proj_w   = (const float*)d_in[4];
    const float* dt_proj_w  = (const float*)d_in[5];
    const float* dt_proj_b  = (const float*)d_in[6];
    const float* A_log      = (const float*)d_in[7];
    const float* Dv         = (const float*)d_in[8];
    const float* conv_w_b   = (const float*)d_in[9];
    const float* conv_b_b   = (const float*)d_in[10];
    const float* x_proj_w_b = (const float*)d_in[11];
    const float* dt_proj_w_b= (const float*)d_in[12];
    const float* dt_proj_b_b= (const float*)d_in[13];
    const float* A_b_log    = (const float*)d_in[14];
    const float* D_b        = (const float*)d_in[15];
    const float* out_proj_w = (const float*)d_in[16];
    float* out = (float*)d_out;

    float *p_xz, *p_delta0, *p_delta1;
    cudaGetSymbolAddress((void**)&p_xz, g_xz);
    cudaGetSymbolAddress((void**)&p_delta0, g_delta0);
    cudaGetSymbolAddress((void**)&p_delta1, g_delta1);
    uint16_t *p_hidh, *p_hidl, *p_w1h, *p_w1l, *p_xwh, *p_xwl, *p_dtwh, *p_dtwl;
    uint16_t *p_owh, *p_owl, *p_xc0h, *p_xc0l, *p_xc1h, *p_xc1l, *p_ysh, *p_ysl;
    cudaGetSymbolAddress((void**)&p_hidh, g_hidh);
    cudaGetSymbolAddress((void**)&p_hidl, g_hidl);
    cudaGetSymbolAddress((void**)&p_w1h, g_w1h);
    cudaGetSymbolAddress((void**)&p_w1l, g_w1l);
    cudaGetSymbolAddress((void**)&p_xwh, g_xwh);
    cudaGetSymbolAddress((void**)&p_xwl, g_xwl);
    cudaGetSymbolAddress((void**)&p_dtwh, g_dtwh);
    cudaGetSymbolAddress((void**)&p_dtwl, g_dtwl);
    cudaGetSymbolAddress((void**)&p_owh, g_owh);
    cudaGetSymbolAddress((void**)&p_owl, g_owl);
    cudaGetSymbolAddress((void**)&p_xc0h, g_xc0h);
    cudaGetSymbolAddress((void**)&p_xc0l, g_xc0l);
    cudaGetSymbolAddress((void**)&p_xc1h, g_xc1h);
    cudaGetSymbolAddress((void**)&p_xc1l, g_xc1l);
    cudaGetSymbolAddress((void**)&p_ysh, g_ysh);
    cudaGetSymbolAddress((void**)&p_ysl, g_ysl);

    cudaFuncSetAttribute(gemm_mma_s<128>, cudaFuncAttributeMaxDynamicSharedMemorySize, 65536);
    cudaFuncSetAttribute(gemm_mma_s<64>,  cudaFuncAttributeMaxDynamicSharedMemorySize, 49152);
    cudaFuncSetAttribute(gemm_mma80b, cudaFuncAttributeMaxDynamicSharedMemorySize, MMA80_SMEM);
    cudaFuncSetAttribute(gemm_mma48b, cudaFuncAttributeMaxDynamicSharedMemorySize, 65536);

    const int M = BB * LL;  // 2048

    // 0) pre-split static tensors to bf16 hi/lo
    {
        SArgs sa{};
        int base = 0;
        auto add = [&](int k, const float* src, uint16_t* hi, uint16_t* lo, int n) {
            sa.s[k] = SSeg{src, hi, lo, base, n / 4};
            base += n / 4;
        };
        add(0, hidden,      p_hidh, p_hidl, M * DM);
        add(1, in_proj_w,   p_w1h,  p_w1l,  2 * DI * DM);
        add(2, x_proj_w,    p_xwh,            p_xwl,            80 * DI);
        add(3, x_proj_w_b,  p_xwh + 80 * DI,  p_xwl + 80 * DI,  80 * DI);
        add(4, dt_proj_w,   p_dtwh,           p_dtwl,           DI * DTR);
        add(5, dt_proj_w_b, p_dtwh + DI * DTR,p_dtwl + DI * DTR,DI * DTR);
        add(6, out_proj_w,  p_owh,  p_owl,  DM * DI);
        sa.total4 = base;
        split_many<<<(base + 255) / 256, 256>>>(sa);
    }

    // 1) xz = hidden @ in_proj_w^T
    {
        TBArgs a{};
        a.Ah = p_hidh; a.Al = p_hidl; a.Bh = p_w1h; a.Bl = p_w1l; a.C = p_xz;
        a.K = DM; a.lda = DM; a.ldb = DM; a.ldc = 2 * DI;
        gemm_mma_s<128><<<dim3(2 * DI / 128, M / 128), 256, 65536>>>(a);
    }

    // 2) conv + silu (+ bf16 split of xc)
    conv_silu_k<<<(unsigned)(((size_t)M * (DI / 4) + 255) / 256), 256>>>(
        conv_w, conv_b, conv_w_b, conv_b_b);

    // 3) x_dbl partials (split-K 4), both branches
    {
        G80B a{};
        a.Ah[0] = p_xc0h; a.Ah[1] = p_xc1h;
        a.Al[0] = p_xc0l; a.Al[1] = p_xc1l;
        gemm_mma80b<<<dim3(1, M / 64, 8), 256, MMA80_SMEM>>>(a);
    }

    // 4) combine partials -> f32 xdbl + bf16 split
    xdbl_combine<<<(2 * (M * 80 / 4) + 255) / 256, 256>>>();

    // 5) delta = softplus(dt @ dt_proj_w^T + bias)
    {
        G48B a{};
        a.C[0] = p_delta0; a.C[1] = p_delta1;
        a.bias[0] = dt_proj_b; a.bias[1] = dt_proj_b_b;
        gemm_mma48b<<<dim3(DI / 128, M / 128, 2), 256, 65536>>>(a);
    }

    // 6) scan pass A
    scan_passA<<<dim3(DI / 128, NSEG - 1, 4), 128>>>(A_log, A_b_log);

    // 7) pass B
    scan_passB<<<(BB * 2 * DI) / 128, 128>>>();

    // 8) pass C
    scan_passC<<<dim3(DI / 128, NSEG, 4), 128>>>(A_log, A_b_log, Dv, D_b);

    // 9) ys sum + split
    ys_split<<<(unsigned)(((size_t)M * DI / 4 + 255) / 256), 256>>>();

    // 10) out = ysum @ out_proj_w^T
    {
        TBArgs a{};
        a.Ah = p_ysh; a.Al = p_ysl; a.Bh = p_owh; a.Bl = p_owl; a.C = out;
        a.K = DI; a.lda = DI; a.ldb = DI; a.ldc = DM;
        gemm_mma_s<64><<<dim3(DM / 64, M / 128), 256, 49152>>>(a);
    }
}